// round 8
// baseline (speedup 1.0000x reference)
#include <cuda_runtime.h>
#include <cuda_bf16.h>
#include <cstdint>

#define NB 1024
#define NV 64
#define NI 256
#define NO 256
constexpr float EPS = 1e-5f;

// ---------------------------------------------------------------------------
// Device scratch
// ---------------------------------------------------------------------------
__device__ float g_h[(size_t)NB * NV * NO];            // 64 MB: h = feat@W + b
__device__ __nv_bfloat16 g_Whi[(size_t)NV * NO * NI];  // 8 MB, layout [v][o][i]
__device__ __nv_bfloat16 g_Wlo[(size_t)NV * NO * NI];  // 8 MB
__device__ __nv_bfloat16 g_adjhi[NV * NV];
__device__ __nv_bfloat16 g_adjlo[NV * NV];
__device__ float g_sum[NV * NO];
__device__ float g_sqs[NV * NO];
__device__ float g_s[NV * NO];
__device__ float g_t[NV * NO];

// ---------------------------------------------------------------------------
// Helpers (baseline PTX only)
// ---------------------------------------------------------------------------
__device__ __forceinline__ uint32_t smem_u32(const void* p) {
    uint32_t a;
    asm("{ .reg .u64 t; cvta.to.shared.u64 t, %1; cvt.u32.u64 %0, t; }"
        : "=r"(a) : "l"(p));
    return a;
}
#define SWZ(off)   ((uint32_t)(off) ^ ((((uint32_t)(off)) >> 3) & 0x70))  // 128B rows
#define SWZ64(off) ((uint32_t)(off) ^ ((((uint32_t)(off)) >> 3) & 0x30))  // 64B rows

__device__ __forceinline__ void ldsm_x4(uint32_t* r, uint32_t addr) {
    asm volatile("ldmatrix.sync.aligned.m8n8.x4.shared.b16 {%0,%1,%2,%3}, [%4];"
                 : "=r"(r[0]), "=r"(r[1]), "=r"(r[2]), "=r"(r[3]) : "r"(addr));
}
__device__ __forceinline__ void ldsm_x2(uint32_t* r, uint32_t addr) {
    asm volatile("ldmatrix.sync.aligned.m8n8.x2.shared.b16 {%0,%1}, [%2];"
                 : "=r"(r[0]), "=r"(r[1]) : "r"(addr));
}
__device__ __forceinline__ void ldsm_x2t(uint32_t* r, uint32_t addr) {
    asm volatile("ldmatrix.sync.aligned.m8n8.x2.trans.shared.b16 {%0,%1}, [%2];"
                 : "=r"(r[0]), "=r"(r[1]) : "r"(addr));
}
__device__ __forceinline__ void mma_bf16(float* d, const uint32_t* a,
                                         const uint32_t* b) {
    asm volatile(
        "mma.sync.aligned.m16n8k16.row.col.f32.bf16.bf16.f32 "
        "{%0,%1,%2,%3}, {%4,%5,%6,%7}, {%8,%9}, {%0,%1,%2,%3};"
        : "+f"(d[0]), "+f"(d[1]), "+f"(d[2]), "+f"(d[3])
        : "r"(a[0]), "r"(a[1]), "r"(a[2]), "r"(a[3]), "r"(b[0]), "r"(b[1]));
}
__device__ __forceinline__ void cp16(uint32_t smem, const void* g) {
    asm volatile("cp.async.cg.shared.global [%0], [%1], 16;"
                 :: "r"(smem), "l"(g) : "memory");
}
#define CP_COMMIT() asm volatile("cp.async.commit_group;" ::: "memory")
#define CP_WAIT(N)  asm volatile("cp.async.wait_group %0;" :: "n"(N) : "memory")

// ---------------------------------------------------------------------------
// Kernel A: split W into bf16 hi/lo, transposed to K-major [v][o][i]
// ---------------------------------------------------------------------------
__global__ __launch_bounds__(256) void convert_W(const float* __restrict__ W) {
    __shared__ float tile[256][65];
    const int v = blockIdx.y, o0 = blockIdx.x * 64;
    const int t = threadIdx.x;
    const float* src = W + (size_t)v * NI * NO + o0;
#pragma unroll 8
    for (int r = 0; r < 64; r++) {
        int idx = r * 256 + t;
        int i = idx >> 6, o = idx & 63;
        tile[i][o] = src[(size_t)i * NO + o];
    }
    __syncthreads();
    __nv_bfloat16* dh = g_Whi + ((size_t)v * NO + o0) * NI;
    __nv_bfloat16* dl = g_Wlo + ((size_t)v * NO + o0) * NI;
#pragma unroll 8
    for (int r = 0; r < 64; r++) {
        float x = tile[t][r];
        __nv_bfloat16 hi = __float2bfloat16(x);
        __nv_bfloat16 lo = __float2bfloat16(x - __bfloat162float(hi));
        dh[(size_t)r * NI + t] = hi;
        dl[(size_t)r * NI + t] = lo;
    }
}

// ---------------------------------------------------------------------------
// Kernel A2: split adj into bf16 hi/lo AND zero stats accumulators.
// ---------------------------------------------------------------------------
__global__ void convert_adj(const float* __restrict__ adj) {
    int i = blockIdx.x * 256 + threadIdx.x;   // 0..4095
    float x = adj[i];
    __nv_bfloat16 hi = __float2bfloat16(x);
    g_adjhi[i] = hi;
    g_adjlo[i] = __float2bfloat16(x - __bfloat162float(hi));
    ((float4*)g_sum)[i] = make_float4(0.f, 0.f, 0.f, 0.f);
    ((float4*)g_sqs)[i] = make_float4(0.f, 0.f, 0.f, 0.f);
}

// ---------------------------------------------------------------------------
// Kernel B: double-buffered mma.sync split-bf16 GEMM + shuffle-reduced stats.
// grid (NB/128, NO/128, NV), block 256 (8 warps), tile 128x128.
// K-chunk 32, 2 stages of 32KB -> occ 2. B via cp.async (1 chunk ahead),
// A via LDG reg-prefetch (1 chunk ahead) + cvt/STS. 64B rows, SW64 swizzle.
// ---------------------------------------------------------------------------
static constexpr int CH = 32;            // k per chunk
static constexpr int NCH = NI / CH;      // 8 chunks
static constexpr int A_HI = 0;           // 128 x 32 bf16 = 8 KB
static constexpr int A_LO = 8192;
static constexpr int B_HI = 16384;
static constexpr int B_LO = 24576;
static constexpr int STG = 32768;
static constexpr int GEMM_DSMEM = 2 * STG + 1024;

__device__ __forceinline__ void load_A_regs(float4* areg,
                                            const float* __restrict__ feat,
                                            int m0, int v, int k0, int t) {
#pragma unroll
    for (int r = 0; r < 4; r++) {
        int idx = t + r * 256;          // 0..1023
        int m = idx >> 3, u8 = idx & 7; // 8B (4-elem) unit within 32k row
        areg[r] = *(const float4*)(feat +
                   ((size_t)(m0 + m) * NV + v) * NI + k0 + u8 * 4);
    }
}
__device__ __forceinline__ void store_A_smem(char* buf, const float4* areg,
                                             int t) {
#pragma unroll
    for (int r = 0; r < 4; r++) {
        int idx = t + r * 256;
        int m = idx >> 3, u8 = idx & 7;
        float4 x = areg[r];
        __nv_bfloat16 h0 = __float2bfloat16(x.x);
        __nv_bfloat16 h1 = __float2bfloat16(x.y);
        __nv_bfloat16 h2 = __float2bfloat16(x.z);
        __nv_bfloat16 h3 = __float2bfloat16(x.w);
        __nv_bfloat16 l0 = __float2bfloat16(x.x - __bfloat162float(h0));
        __nv_bfloat16 l1 = __float2bfloat16(x.y - __bfloat162float(h1));
        __nv_bfloat16 l2 = __float2bfloat16(x.z - __bfloat162float(h2));
        __nv_bfloat16 l3 = __float2bfloat16(x.w - __bfloat162float(h3));
        uint32_t off = SWZ64(m * 64 + u8 * 8);
        __nv_bfloat162 hp0 = {h0, h1}, hp1 = {h2, h3};
        __nv_bfloat162 lp0 = {l0, l1}, lp1 = {l2, l3};
        *(uint2*)(buf + A_HI + off) =
            make_uint2(*(uint32_t*)&hp0, *(uint32_t*)&hp1);
        *(uint2*)(buf + A_LO + off) =
            make_uint2(*(uint32_t*)&lp0, *(uint32_t*)&lp1);
    }
}
__device__ __forceinline__ void issue_B(uint32_t sb,
                                        const __nv_bfloat16* __restrict__ Wh,
                                        const __nv_bfloat16* __restrict__ Wl,
                                        int k0, int t) {
#pragma unroll
    for (int r = 0; r < 2; r++) {
        int idx = t + r * 256;          // 0..511 16B chunks
        int n = idx >> 2, c16 = idx & 3;
        uint32_t off = SWZ64(n * 64 + c16 * 16);
        cp16(sb + B_HI + off, Wh + (size_t)n * NI + k0 + c16 * 8);
        cp16(sb + B_LO + off, Wl + (size_t)n * NI + k0 + c16 * 8);
    }
}

__global__ __launch_bounds__(256, 2) void gemm_mma(const float* __restrict__ feat,
                                                   const float* __restrict__ bias) {
    extern __shared__ char dynraw[];
    uint32_t rawa = smem_u32(dynraw);
    char* smb = dynraw + (((rawa + 1023) & ~1023u) - rawa);
    const uint32_t sb0 = smem_u32(smb);

    const int v  = blockIdx.z;
    const int m0 = blockIdx.x * 128;
    const int n0 = blockIdx.y * 128;
    const int t  = threadIdx.x;
    const int lane = t & 31;
    const int w = t >> 5;
    const int mw = (w >> 2) * 64;
    const int nw = (w & 3) * 32;

    float acc[4][4][4];
#pragma unroll
    for (int i = 0; i < 4; i++)
#pragma unroll
        for (int j = 0; j < 4; j++)
#pragma unroll
            for (int q = 0; q < 4; q++) acc[i][j][q] = 0.f;

    const __nv_bfloat16* Wh = g_Whi + ((size_t)v * NO + n0) * NI;
    const __nv_bfloat16* Wl = g_Wlo + ((size_t)v * NO + n0) * NI;

    // ---- prologue: fill stage0 (chunk0), start stage1 (chunk1)
    float4 areg[4];
    load_A_regs(areg, feat, m0, v, 0, t);
    issue_B(sb0, Wh, Wl, 0, t);
    CP_COMMIT();                               // group 0 (B chunk0)
    store_A_smem(smb, areg, t);
    load_A_regs(areg, feat, m0, v, CH, t);     // A chunk1 -> regs
    issue_B(sb0 + STG, Wh, Wl, CH, t);
    CP_COMMIT();                               // group 1 (B chunk1)
    CP_WAIT(1);                                // B chunk0 ready
    __syncthreads();

#pragma unroll
    for (int c = 0; c < NCH; c++) {
        const uint32_t sb = sb0 + (c & 1) * STG;

        // ---- compute chunk c (2 k-steps of 16)
#pragma unroll
        for (int ks = 0; ks < 2; ks++) {
            uint32_t bh[4][2], bl[4][2];
            {
                int brow = nw + (lane & 7);
                int bcol = ks * 32 + ((lane >> 3) & 1) * 16;   // bytes
#pragma unroll
                for (int nt = 0; nt < 4; nt++) {
                    uint32_t addr = sb + B_HI + SWZ64((brow + nt * 8) * 64 + bcol);
                    ldsm_x2(bh[nt], addr);
                    ldsm_x2(bl[nt], addr + (B_LO - B_HI));
                }
            }
            int arow = mw + (lane & 7) + ((lane >> 3) & 1) * 8;
            int acol = ks * 32 + ((lane >> 4) & 1) * 16;       // bytes
#pragma unroll
            for (int mt = 0; mt < 4; mt++) {
                uint32_t ra[4], rl[4];
                uint32_t addr = sb + A_HI + SWZ64((arow + mt * 16) * 64 + acol);
                ldsm_x4(ra, addr);
                ldsm_x4(rl, addr + (A_LO - A_HI));
#pragma unroll
                for (int nt = 0; nt < 4; nt++) {
                    mma_bf16(acc[mt][nt], ra, bh[nt]);
                    mma_bf16(acc[mt][nt], ra, bl[nt]);
                    mma_bf16(acc[mt][nt], rl, bh[nt]);
                }
            }
        }

        if (c < NCH - 1) {
            __syncthreads();                        // everyone done with chunk c
            // A chunk c+1 (in regs) -> stage (c+1)&1
            store_A_smem(smb + ((c + 1) & 1) * STG, areg, t);
            if (c < NCH - 2) {
                load_A_regs(areg, feat, m0, v, (c + 2) * CH, t);  // prefetch A
                issue_B(sb0 + (c & 1) * STG, Wh, Wl, (c + 2) * CH, t);
                CP_COMMIT();                        // group c+2
                CP_WAIT(1);                         // B chunk c+1 ready
            } else {
                CP_WAIT(0);                         // last B ready
            }
            __syncthreads();
        }
    }

    // ---- epilogue: bias + store h + shuffle-reduced column stats
#pragma unroll
    for (int nt = 0; nt < 4; nt++) {
        const int nl = nw + nt * 8 + (lane & 3) * 2;   // col in block tile
        const int n = n0 + nl;
        float2 bv = *(const float2*)(bias + v * NO + n);
        float2 sum2 = make_float2(0.f, 0.f), sq2 = make_float2(0.f, 0.f);
#pragma unroll
        for (int mt = 0; mt < 4; mt++) {
            int mlo = m0 + mw + mt * 16 + (lane >> 2);
            float2 o0, o1;
            o0.x = acc[mt][nt][0] + bv.x;
            o0.y = acc[mt][nt][1] + bv.y;
            o1.x = acc[mt][nt][2] + bv.x;
            o1.y = acc[mt][nt][3] + bv.y;
            *(float2*)(g_h + (size_t)mlo * (NV * NO) + v * NO + n) = o0;
            *(float2*)(g_h + (size_t)(mlo + 8) * (NV * NO) + v * NO + n) = o1;
            sum2.x += o0.x + o1.x;
            sum2.y += o0.y + o1.y;
            sq2.x += fmaf(o0.x, o0.x, o1.x * o1.x);
            sq2.y += fmaf(o0.y, o0.y, o1.y * o1.y);
        }
#pragma unroll
        for (int msk = 4; msk <= 16; msk <<= 1) {
            sum2.x += __shfl_xor_sync(0xffffffffu, sum2.x, msk);
            sum2.y += __shfl_xor_sync(0xffffffffu, sum2.y, msk);
            sq2.x  += __shfl_xor_sync(0xffffffffu, sq2.x, msk);
            sq2.y  += __shfl_xor_sync(0xffffffffu, sq2.y, msk);
        }
        if (lane < 4) {
            atomicAdd(&g_sum[v * NO + n],     sum2.x);
            atomicAdd(&g_sum[v * NO + n + 1], sum2.y);
            atomicAdd(&g_sqs[v * NO + n],     sq2.x);
            atomicAdd(&g_sqs[v * NO + n + 1], sq2.y);
        }
    }
}

// ---------------------------------------------------------------------------
// Kernel C: finalize BN fold
// ---------------------------------------------------------------------------
__global__ __launch_bounds__(256) void stats_fin(const float* __restrict__ gamma,
                                                 const float* __restrict__ beta) {
    const int col = blockIdx.x * 256 + threadIdx.x;
    float mean = g_sum[col] * (1.f / NB);
    float var  = g_sqs[col] * (1.f / NB) - mean * mean;
    float s    = gamma[col] * rsqrtf(var + EPS);
    g_s[col] = s;
    g_t[col] = fmaf(-mean, s, beta[col]);
}

// ---------------------------------------------------------------------------
// Kernel D: tensorized mix
// ---------------------------------------------------------------------------
static constexpr int OPAD = 264;
static constexpr int HS_HI = 0;
static constexpr int HS_LO = 33792;
static constexpr int ADJ_HI = 67584;
static constexpr int ADJ_LO = 76800;
static constexpr int MIX_DSMEM = 86016 + 1024;

__global__ __launch_bounds__(256, 2) void mix_tc(float* __restrict__ out) {
    extern __shared__ char dynraw[];
    uint32_t rawa = smem_u32(dynraw);
    char* smb = dynraw + (((rawa + 1023) & ~1023u) - rawa);
    const uint32_t sbase = smem_u32(smb);

    const int b = blockIdx.x;
    const int t = threadIdx.x;
    const int lane = t & 31;
    const int w = t >> 5;

    const float4* h4 = (const float4*)(g_h + (size_t)b * NV * NO);
    const float4* s4 = (const float4*)g_s;
    const float4* t4 = (const float4*)g_t;
#pragma unroll
    for (int r = 0; r < 16; r++) {
        int idx = t + r * 256;
        int v = idx >> 6, oq = idx & 63;
        float4 h = h4[idx], sv = s4[idx], tv = t4[idx];
        float x0 = fmaf(h.x, sv.x, tv.x);
        float x1 = fmaf(h.y, sv.y, tv.y);
        float x2 = fmaf(h.z, sv.z, tv.z);
        float x3 = fmaf(h.w, sv.w, tv.w);
        __nv_bfloat16 h0 = __float2bfloat16(x0);
        __nv_bfloat16 h1 = __float2bfloat16(x1);
        __nv_bfloat16 h2 = __float2bfloat16(x2);
        __nv_bfloat16 h3 = __float2bfloat16(x3);
        __nv_bfloat16 l0 = __float2bfloat16(x0 - __bfloat162float(h0));
        __nv_bfloat16 l1 = __float2bfloat16(x1 - __bfloat162float(h1));
        __nv_bfloat16 l2 = __float2bfloat16(x2 - __bfloat162float(h2));
        __nv_bfloat16 l3 = __float2bfloat16(x3 - __bfloat162float(h3));
        __nv_bfloat162 hp0 = {h0, h1}, hp1 = {h2, h3};
        __nv_bfloat162 lp0 = {l0, l1}, lp1 = {l2, l3};
        uint32_t off = (uint32_t)(v * (OPAD * 2) + oq * 8);
        *(uint2*)(smb + HS_HI + off) =
            make_uint2(*(uint32_t*)&hp0, *(uint32_t*)&hp1);
        *(uint2*)(smb + HS_LO + off) =
            make_uint2(*(uint32_t*)&lp0, *(uint32_t*)&lp1);
    }
#pragma unroll
    for (int r = 0; r < 8; r++) {
        int idx = t + r * 256;
        int u = idx >> 5, q = idx & 31;
        *(uint32_t*)(smb + ADJ_HI + u * 144 + q * 4) =
            ((const uint32_t*)g_adjhi)[idx];
        *(uint32_t*)(smb + ADJ_LO + u * 144 + q * 4) =
            ((const uint32_t*)g_adjlo)[idx];
    }
    __syncthreads();

    const int mw = (w >> 1) * 16;
    const int nw = (w & 1) * 128;

    float acc[16][4];
#pragma unroll
    for (int i = 0; i < 16; i++)
#pragma unroll
        for (int q = 0; q < 4; q++) acc[i][q] = 0.f;

#pragma unroll
    for (int ks = 0; ks < 4; ks++) {
        uint32_t ah[4], al[4];
        uint32_t aaddr = sbase + ADJ_HI + (mw + (lane & 15)) * 144 +
                         (ks * 16 + (lane >> 4) * 8) * 2;
        ldsm_x4(ah, aaddr);
        ldsm_x4(al, aaddr + (ADJ_LO - ADJ_HI));

        uint32_t brow = sbase + HS_HI + (ks * 16 + (lane & 15)) * (OPAD * 2);
#pragma unroll
        for (int nt = 0; nt < 16; nt++) {
            int n0 = nw + nt * 8;
            uint32_t bh[2], bl[2];
            ldsm_x2t(bh, brow + n0 * 2);
            ldsm_x2t(bl, brow + n0 * 2 + (HS_LO - HS_HI));
            mma_bf16(acc[nt], ah, bh);
            mma_bf16(acc[nt], ah, bl);
            mma_bf16(acc[nt], al, bh);
        }
    }

    float* ob = out + (size_t)b * NV * NO;
    const int u0 = mw + (lane >> 2);
#pragma unroll
    for (int nt = 0; nt < 16; nt++) {
        int o = nw + nt * 8 + (lane & 3) * 2;
        float2 r0, r1;
        r0.x = fmaxf(acc[nt][0], 0.f);
        r0.y = fmaxf(acc[nt][1], 0.f);
        r1.x = fmaxf(acc[nt][2], 0.f);
        r1.y = fmaxf(acc[nt][3], 0.f);
        *(float2*)(ob + (size_t)u0 * NO + o) = r0;
        *(float2*)(ob + (size_t)(u0 + 8) * NO + o) = r1;
    }
}

// ---------------------------------------------------------------------------
extern "C" void kernel_launch(void* const* d_in, const int* in_sizes, int n_in,
                              void* d_out, int out_size) {
    const float* feat  = (const float*)d_in[0];
    const float* adj   = (const float*)d_in[1];
    const float* W     = (const float*)d_in[2];
    const float* bias  = (const float*)d_in[3];
    const float* gamma = (const float*)d_in[4];
    const float* beta  = (const float*)d_in[5];
    float* out = (float*)d_out;

    cudaFuncSetAttribute(gemm_mma, cudaFuncAttributeMaxDynamicSharedMemorySize,
                         GEMM_DSMEM);
    cudaFuncSetAttribute(mix_tc, cudaFuncAttributeMaxDynamicSharedMemorySize,
                         MIX_DSMEM);

    convert_W<<<dim3(NO / 64, NV), 256>>>(W);
    convert_adj<<<16, 256>>>(adj);   // also zeroes g_sum/g_sqs
    gemm_mma<<<dim3(NB / 128, NO / 128, NV), 256, GEMM_DSMEM>>>(feat, bias);
    stats_fin<<<64, 256>>>(gamma, beta);
    mix_tc<<<NB, 256, MIX_DSMEM>>>(out);
}

// round 9
// speedup vs baseline: 1.0596x; 1.0596x over previous
#include <cuda_runtime.h>
#include <cuda_bf16.h>
#include <cstdint>

#define NB 1024
#define NV 64
#define NI 256
#define NO 256
constexpr float EPS = 1e-5f;

// ---------------------------------------------------------------------------
// Device scratch
// ---------------------------------------------------------------------------
__device__ float g_h[(size_t)NB * NV * NO];            // 64 MB: h = feat@W + b
__device__ __nv_bfloat16 g_Whi[(size_t)NV * NO * NI];  // 8 MB, layout [v][o][i]
__device__ __nv_bfloat16 g_Wlo[(size_t)NV * NO * NI];  // 8 MB
__device__ __nv_bfloat16 g_adjhi[NV * NV];
__device__ __nv_bfloat16 g_adjlo[NV * NV];
__device__ float g_sum[NV * NO];
__device__ float g_sqs[NV * NO];
__device__ float g_s[NV * NO];
__device__ float g_t[NV * NO];

// ---------------------------------------------------------------------------
// Helpers (baseline PTX only)
// ---------------------------------------------------------------------------
__device__ __forceinline__ uint32_t smem_u32(const void* p) {
    uint32_t a;
    asm("{ .reg .u64 t; cvta.to.shared.u64 t, %1; cvt.u32.u64 %0, t; }"
        : "=r"(a) : "l"(p));
    return a;
}
#define SWZ(off) ((uint32_t)(off) ^ ((((uint32_t)(off)) >> 3) & 0x70))  // 128B rows

__device__ __forceinline__ void ldsm_x4(uint32_t* r, uint32_t addr) {
    asm volatile("ldmatrix.sync.aligned.m8n8.x4.shared.b16 {%0,%1,%2,%3}, [%4];"
                 : "=r"(r[0]), "=r"(r[1]), "=r"(r[2]), "=r"(r[3]) : "r"(addr));
}
__device__ __forceinline__ void ldsm_x2(uint32_t* r, uint32_t addr) {
    asm volatile("ldmatrix.sync.aligned.m8n8.x2.shared.b16 {%0,%1}, [%2];"
                 : "=r"(r[0]), "=r"(r[1]) : "r"(addr));
}
__device__ __forceinline__ void ldsm_x2t(uint32_t* r, uint32_t addr) {
    asm volatile("ldmatrix.sync.aligned.m8n8.x2.trans.shared.b16 {%0,%1}, [%2];"
                 : "=r"(r[0]), "=r"(r[1]) : "r"(addr));
}
__device__ __forceinline__ void mma_bf16(float* d, const uint32_t* a,
                                         const uint32_t* b) {
    asm volatile(
        "mma.sync.aligned.m16n8k16.row.col.f32.bf16.bf16.f32 "
        "{%0,%1,%2,%3}, {%4,%5,%6,%7}, {%8,%9}, {%0,%1,%2,%3};"
        : "+f"(d[0]), "+f"(d[1]), "+f"(d[2]), "+f"(d[3])
        : "r"(a[0]), "r"(a[1]), "r"(a[2]), "r"(a[3]), "r"(b[0]), "r"(b[1]));
}
__device__ __forceinline__ void cp16(uint32_t smem, const void* g) {
    asm volatile("cp.async.cg.shared.global [%0], [%1], 16;"
                 :: "r"(smem), "l"(g) : "memory");
}
#define CP_COMMIT() asm volatile("cp.async.commit_group;" ::: "memory")
#define CP_WAIT(N)  asm volatile("cp.async.wait_group %0;" :: "n"(N) : "memory")

// ---------------------------------------------------------------------------
// Kernel A: split W into bf16 hi/lo, transposed to K-major [v][o][i]
// ---------------------------------------------------------------------------
__global__ __launch_bounds__(256) void convert_W(const float* __restrict__ W) {
    __shared__ float tile[256][65];
    const int v = blockIdx.y, o0 = blockIdx.x * 64;
    const int t = threadIdx.x;
    const float* src = W + (size_t)v * NI * NO + o0;
#pragma unroll 8
    for (int r = 0; r < 64; r++) {
        int idx = r * 256 + t;
        int i = idx >> 6, o = idx & 63;
        tile[i][o] = src[(size_t)i * NO + o];
    }
    __syncthreads();
    __nv_bfloat16* dh = g_Whi + ((size_t)v * NO + o0) * NI;
    __nv_bfloat16* dl = g_Wlo + ((size_t)v * NO + o0) * NI;
#pragma unroll 8
    for (int r = 0; r < 64; r++) {
        float x = tile[t][r];
        __nv_bfloat16 hi = __float2bfloat16(x);
        __nv_bfloat16 lo = __float2bfloat16(x - __bfloat162float(hi));
        dh[(size_t)r * NI + t] = hi;
        dl[(size_t)r * NI + t] = lo;
    }
}

// ---------------------------------------------------------------------------
// Kernel A2: split adj into bf16 hi/lo AND zero stats accumulators.
// ---------------------------------------------------------------------------
__global__ void convert_adj(const float* __restrict__ adj) {
    int i = blockIdx.x * 256 + threadIdx.x;   // 0..4095
    float x = adj[i];
    __nv_bfloat16 hi = __float2bfloat16(x);
    g_adjhi[i] = hi;
    g_adjlo[i] = __float2bfloat16(x - __bfloat162float(hi));
    ((float4*)g_sum)[i] = make_float4(0.f, 0.f, 0.f, 0.f);
    ((float4*)g_sqs)[i] = make_float4(0.f, 0.f, 0.f, 0.f);
}

// ---------------------------------------------------------------------------
// Kernel B: 3-stage-ring mma.sync split-bf16 GEMM + shuffle-reduced stats.
// grid (NB/128, NO/128, NV), block 256 (8 warps), tile 128x128.
// K-chunk 32. Stage layout: A rows m: [hi 64B | lo 64B] (128B, SW128);
// B rows n: same. 3 stages x 32KB = 96KB -> occ 2. One sync per chunk.
// ---------------------------------------------------------------------------
static constexpr int CH = 32;            // k per chunk
static constexpr int NCH = NI / CH;      // 8 chunks
static constexpr int A_OFF = 0;          // 128 rows x 128B = 16 KB
static constexpr int B_OFF = 16384;      // 128 rows x 128B = 16 KB
static constexpr int STG = 32768;
static constexpr int GEMM_DSMEM = 3 * STG + 1024;

__device__ __forceinline__ void load_A_regs(float4* areg,
                                            const float* __restrict__ feat,
                                            int m0, int v, int k0, int t) {
#pragma unroll
    for (int r = 0; r < 4; r++) {
        int idx = t + r * 256;          // 0..1023
        int m = idx >> 3, u8 = idx & 7; // float4 unit within 32-k row
        areg[r] = *(const float4*)(feat +
                   ((size_t)(m0 + m) * NV + v) * NI + k0 + u8 * 4);
    }
}
// A row m: bytes [0,64) = hi(32 bf16), [64,128) = lo(32 bf16); SW128 swizzled.
__device__ __forceinline__ void store_A_smem(char* buf, const float4* areg,
                                             int t) {
#pragma unroll
    for (int r = 0; r < 4; r++) {
        int idx = t + r * 256;
        int m = idx >> 3, u8 = idx & 7;
        float4 x = areg[r];
        __nv_bfloat16 h0 = __float2bfloat16(x.x);
        __nv_bfloat16 h1 = __float2bfloat16(x.y);
        __nv_bfloat16 h2 = __float2bfloat16(x.z);
        __nv_bfloat16 h3 = __float2bfloat16(x.w);
        __nv_bfloat16 l0 = __float2bfloat16(x.x - __bfloat162float(h0));
        __nv_bfloat16 l1 = __float2bfloat16(x.y - __bfloat162float(h1));
        __nv_bfloat16 l2 = __float2bfloat16(x.z - __bfloat162float(h2));
        __nv_bfloat16 l3 = __float2bfloat16(x.w - __bfloat162float(h3));
        __nv_bfloat162 hp0 = {h0, h1}, hp1 = {h2, h3};
        __nv_bfloat162 lp0 = {l0, l1}, lp1 = {l2, l3};
        uint32_t offh = SWZ(m * 128 + u8 * 8);
        uint32_t offl = SWZ(m * 128 + 64 + u8 * 8);
        *(uint2*)(buf + A_OFF + offh) =
            make_uint2(*(uint32_t*)&hp0, *(uint32_t*)&hp1);
        *(uint2*)(buf + A_OFF + offl) =
            make_uint2(*(uint32_t*)&lp0, *(uint32_t*)&lp1);
    }
}
// B row n: [hi 64B | lo 64B], SW128.
__device__ __forceinline__ void issue_B(uint32_t sb,
                                        const __nv_bfloat16* __restrict__ Wh,
                                        const __nv_bfloat16* __restrict__ Wl,
                                        int k0, int t) {
#pragma unroll
    for (int r = 0; r < 2; r++) {
        int idx = t + r * 256;          // 0..511
        int n = idx >> 2, c16 = idx & 3;
        cp16(sb + B_OFF + SWZ(n * 128 + c16 * 16),
             Wh + (size_t)n * NI + k0 + c16 * 8);
        cp16(sb + B_OFF + SWZ(n * 128 + 64 + c16 * 16),
             Wl + (size_t)n * NI + k0 + c16 * 8);
    }
}

__global__ __launch_bounds__(256, 2) void gemm_mma(const float* __restrict__ feat,
                                                   const float* __restrict__ bias) {
    extern __shared__ char dynraw[];
    uint32_t rawa = smem_u32(dynraw);
    char* smb = dynraw + (((rawa + 1023) & ~1023u) - rawa);
    const uint32_t sb0 = smem_u32(smb);

    const int v  = blockIdx.z;
    const int m0 = blockIdx.x * 128;
    const int n0 = blockIdx.y * 128;
    const int t  = threadIdx.x;
    const int lane = t & 31;
    const int w = t >> 5;
    const int mw = (w >> 2) * 64;
    const int nw = (w & 3) * 32;

    float acc[4][4][4];
#pragma unroll
    for (int i = 0; i < 4; i++)
#pragma unroll
        for (int j = 0; j < 4; j++)
#pragma unroll
            for (int q = 0; q < 4; q++) acc[i][j][q] = 0.f;

    const __nv_bfloat16* Wh = g_Whi + ((size_t)v * NO + n0) * NI;
    const __nv_bfloat16* Wl = g_Wlo + ((size_t)v * NO + n0) * NI;

    // ---- prologue: chunks 0 and 1 staged, A2 in regs
    float4 areg[4];
    load_A_regs(areg, feat, m0, v, 0, t);
    issue_B(sb0, Wh, Wl, 0, t);
    CP_COMMIT();                                // group 0 = B0
    store_A_smem(smb, areg, t);                 // A0 -> stage 0
    load_A_regs(areg, feat, m0, v, CH, t);
    issue_B(sb0 + STG, Wh, Wl, CH, t);
    CP_COMMIT();                                // group 1 = B1
    store_A_smem(smb + STG, areg, t);           // A1 -> stage 1
    load_A_regs(areg, feat, m0, v, 2 * CH, t);  // A2 -> regs

#pragma unroll
    for (int c = 0; c < NCH; c++) {
        const uint32_t sb = sb0 + (c % 3) * STG;

        if (c < NCH - 1) { CP_WAIT(1); } else { CP_WAIT(0); }
        __syncthreads();   // gates: B_c visible to all; chunk c-1 consumers done

        if (c + 2 < NCH) {
            char* nbuf = smb + ((c + 2) % 3) * STG;
            store_A_smem(nbuf, areg, t);                       // A(c+2)
            if (c + 3 < NCH)
                load_A_regs(areg, feat, m0, v, (c + 3) * CH, t);
            issue_B(sb0 + ((c + 2) % 3) * STG, Wh, Wl, (c + 2) * CH, t);
            CP_COMMIT();                                       // group c+2
        }

        // ---- compute chunk c (2 k-steps of 16)
#pragma unroll
        for (int ks = 0; ks < 2; ks++) {
            uint32_t bh[4][2], bl[4][2];
            {
                int brow = nw + (lane & 7);
                int bcol = ks * 32 + ((lane >> 3) & 1) * 16;   // bytes in hi half
#pragma unroll
                for (int nt = 0; nt < 4; nt++) {
                    uint32_t base = sb + B_OFF;
                    ldsm_x2(bh[nt], base + SWZ((brow + nt * 8) * 128 + bcol));
                    ldsm_x2(bl[nt], base + SWZ((brow + nt * 8) * 128 + 64 + bcol));
                }
            }
            int arow = mw + (lane & 7) + ((lane >> 3) & 1) * 8;
            int acol = ks * 32 + ((lane >> 4) & 1) * 16;       // bytes in hi half
#pragma unroll
            for (int mt = 0; mt < 4; mt++) {
                uint32_t ra[4], rl[4];
                uint32_t base = sb + A_OFF;
                ldsm_x4(ra, base + SWZ((arow + mt * 16) * 128 + acol));
                ldsm_x4(rl, base + SWZ((arow + mt * 16) * 128 + 64 + acol));
#pragma unroll
                for (int nt = 0; nt < 4; nt++) {
                    mma_bf16(acc[mt][nt], ra, bh[nt]);
                    mma_bf16(acc[mt][nt], ra, bl[nt]);
                    mma_bf16(acc[mt][nt], rl, bh[nt]);
                }
            }
        }
    }

    // ---- epilogue: bias + store h + shuffle-reduced column stats
#pragma unroll
    for (int nt = 0; nt < 4; nt++) {
        const int nl = nw + nt * 8 + (lane & 3) * 2;   // col in block tile
        const int n = n0 + nl;
        float2 bv = *(const float2*)(bias + v * NO + n);
        float2 sum2 = make_float2(0.f, 0.f), sq2 = make_float2(0.f, 0.f);
#pragma unroll
        for (int mt = 0; mt < 4; mt++) {
            int mlo = m0 + mw + mt * 16 + (lane >> 2);
            float2 o0, o1;
            o0.x = acc[mt][nt][0] + bv.x;
            o0.y = acc[mt][nt][1] + bv.y;
            o1.x = acc[mt][nt][2] + bv.x;
            o1.y = acc[mt][nt][3] + bv.y;
            *(float2*)(g_h + (size_t)mlo * (NV * NO) + v * NO + n) = o0;
            *(float2*)(g_h + (size_t)(mlo + 8) * (NV * NO) + v * NO + n) = o1;
            sum2.x += o0.x + o1.x;
            sum2.y += o0.y + o1.y;
            sq2.x += fmaf(o0.x, o0.x, o1.x * o1.x);
            sq2.y += fmaf(o0.y, o0.y, o1.y * o1.y);
        }
#pragma unroll
        for (int msk = 4; msk <= 16; msk <<= 1) {
            sum2.x += __shfl_xor_sync(0xffffffffu, sum2.x, msk);
            sum2.y += __shfl_xor_sync(0xffffffffu, sum2.y, msk);
            sq2.x  += __shfl_xor_sync(0xffffffffu, sq2.x, msk);
            sq2.y  += __shfl_xor_sync(0xffffffffu, sq2.y, msk);
        }
        if (lane < 4) {
            atomicAdd(&g_sum[v * NO + n],     sum2.x);
            atomicAdd(&g_sum[v * NO + n + 1], sum2.y);
            atomicAdd(&g_sqs[v * NO + n],     sq2.x);
            atomicAdd(&g_sqs[v * NO + n + 1], sq2.y);
        }
    }
}

// ---------------------------------------------------------------------------
// Kernel C: finalize BN fold
// ---------------------------------------------------------------------------
__global__ __launch_bounds__(256) void stats_fin(const float* __restrict__ gamma,
                                                 const float* __restrict__ beta) {
    const int col = blockIdx.x * 256 + threadIdx.x;
    float mean = g_sum[col] * (1.f / NB);
    float var  = g_sqs[col] * (1.f / NB) - mean * mean;
    float s    = gamma[col] * rsqrtf(var + EPS);
    g_s[col] = s;
    g_t[col] = fmaf(-mean, s, beta[col]);
}

// ---------------------------------------------------------------------------
// Kernel D: tensorized mix
// ---------------------------------------------------------------------------
static constexpr int OPAD = 264;
static constexpr int HS_HI = 0;
static constexpr int HS_LO = 33792;
static constexpr int ADJ_HI = 67584;
static constexpr int ADJ_LO = 76800;
static constexpr int MIX_DSMEM = 86016 + 1024;

__global__ __launch_bounds__(256, 2) void mix_tc(float* __restrict__ out) {
    extern __shared__ char dynraw[];
    uint32_t rawa = smem_u32(dynraw);
    char* smb = dynraw + (((rawa + 1023) & ~1023u) - rawa);
    const uint32_t sbase = smem_u32(smb);

    const int b = blockIdx.x;
    const int t = threadIdx.x;
    const int lane = t & 31;
    const int w = t >> 5;

    const float4* h4 = (const float4*)(g_h + (size_t)b * NV * NO);
    const float4* s4 = (const float4*)g_s;
    const float4* t4 = (const float4*)g_t;
#pragma unroll
    for (int r = 0; r < 16; r++) {
        int idx = t + r * 256;
        int v = idx >> 6, oq = idx & 63;
        float4 h = h4[idx], sv = s4[idx], tv = t4[idx];
        float x0 = fmaf(h.x, sv.x, tv.x);
        float x1 = fmaf(h.y, sv.y, tv.y);
        float x2 = fmaf(h.z, sv.z, tv.z);
        float x3 = fmaf(h.w, sv.w, tv.w);
        __nv_bfloat16 h0 = __float2bfloat16(x0);
        __nv_bfloat16 h1 = __float2bfloat16(x1);
        __nv_bfloat16 h2 = __float2bfloat16(x2);
        __nv_bfloat16 h3 = __float2bfloat16(x3);
        __nv_bfloat16 l0 = __float2bfloat16(x0 - __bfloat162float(h0));
        __nv_bfloat16 l1 = __float2bfloat16(x1 - __bfloat162float(h1));
        __nv_bfloat16 l2 = __float2bfloat16(x2 - __bfloat162float(h2));
        __nv_bfloat16 l3 = __float2bfloat16(x3 - __bfloat162float(h3));
        __nv_bfloat162 hp0 = {h0, h1}, hp1 = {h2, h3};
        __nv_bfloat162 lp0 = {l0, l1}, lp1 = {l2, l3};
        uint32_t off = (uint32_t)(v * (OPAD * 2) + oq * 8);
        *(uint2*)(smb + HS_HI + off) =
            make_uint2(*(uint32_t*)&hp0, *(uint32_t*)&hp1);
        *(uint2*)(smb + HS_LO + off) =
            make_uint2(*(uint32_t*)&lp0, *(uint32_t*)&lp1);
    }
#pragma unroll
    for (int r = 0; r < 8; r++) {
        int idx = t + r * 256;
        int u = idx >> 5, q = idx & 31;
        *(uint32_t*)(smb + ADJ_HI + u * 144 + q * 4) =
            ((const uint32_t*)g_adjhi)[idx];
        *(uint32_t*)(smb + ADJ_LO + u * 144 + q * 4) =
            ((const uint32_t*)g_adjlo)[idx];
    }
    __syncthreads();

    const int mw = (w >> 1) * 16;
    const int nw = (w & 1) * 128;

    float acc[16][4];
#pragma unroll
    for (int i = 0; i < 16; i++)
#pragma unroll
        for (int q = 0; q < 4; q++) acc[i][q] = 0.f;

#pragma unroll
    for (int ks = 0; ks < 4; ks++) {
        uint32_t ah[4], al[4];
        uint32_t aaddr = sbase + ADJ_HI + (mw + (lane & 15)) * 144 +
                         (ks * 16 + (lane >> 4) * 8) * 2;
        ldsm_x4(ah, aaddr);
        ldsm_x4(al, aaddr + (ADJ_LO - ADJ_HI));

        uint32_t brow = sbase + HS_HI + (ks * 16 + (lane & 15)) * (OPAD * 2);
#pragma unroll
        for (int nt = 0; nt < 16; nt++) {
            int n0 = nw + nt * 8;
            uint32_t bh[2], bl[2];
            ldsm_x2t(bh, brow + n0 * 2);
            ldsm_x2t(bl, brow + n0 * 2 + (HS_LO - HS_HI));
            mma_bf16(acc[nt], ah, bh);
            mma_bf16(acc[nt], ah, bl);
            mma_bf16(acc[nt], al, bh);
        }
    }

    float* ob = out + (size_t)b * NV * NO;
    const int u0 = mw + (lane >> 2);
#pragma unroll
    for (int nt = 0; nt < 16; nt++) {
        int o = nw + nt * 8 + (lane & 3) * 2;
        float2 r0, r1;
        r0.x = fmaxf(acc[nt][0], 0.f);
        r0.y = fmaxf(acc[nt][1], 0.f);
        r1.x = fmaxf(acc[nt][2], 0.f);
        r1.y = fmaxf(acc[nt][3], 0.f);
        *(float2*)(ob + (size_t)u0 * NO + o) = r0;
        *(float2*)(ob + (size_t)(u0 + 8) * NO + o) = r1;
    }
}

// ---------------------------------------------------------------------------
extern "C" void kernel_launch(void* const* d_in, const int* in_sizes, int n_in,
                              void* d_out, int out_size) {
    const float* feat  = (const float*)d_in[0];
    const float* adj   = (const float*)d_in[1];
    const float* W     = (const float*)d_in[2];
    const float* bias  = (const float*)d_in[3];
    const float* gamma = (const float*)d_in[4];
    const float* beta  = (const float*)d_in[5];
    float* out = (float*)d_out;

    cudaFuncSetAttribute(gemm_mma, cudaFuncAttributeMaxDynamicSharedMemorySize,
                         GEMM_DSMEM);
    cudaFuncSetAttribute(mix_tc, cudaFuncAttributeMaxDynamicSharedMemorySize,
                         MIX_DSMEM);

    convert_W<<<dim3(NO / 64, NV), 256>>>(W);
    convert_adj<<<16, 256>>>(adj);   // also zeroes g_sum/g_sqs
    gemm_mma<<<dim3(NB / 128, NO / 128, NV), 256, GEMM_DSMEM>>>(feat, bias);
    stats_fin<<<64, 256>>>(gamma, beta);
    mix_tc<<<NB, 256, MIX_DSMEM>>>(out);
}

// round 10
// speedup vs baseline: 1.2286x; 1.1594x over previous
#include <cuda_runtime.h>
#include <cuda_bf16.h>
#include <cuda_fp16.h>
#include <cstdint>

#define NB 1024
#define NV 64
#define NI 256
#define NO 256
constexpr float EPS = 1e-5f;

// ---------------------------------------------------------------------------
// Device scratch
// ---------------------------------------------------------------------------
__device__ float g_h[(size_t)NB * NV * NO];            // 64 MB: h = feat@W + b
__device__ __half g_Whi[(size_t)NV * NO * NI];         // 8 MB, layout [v][o][i]
__device__ __half g_Wlo[(size_t)NV * NO * NI];         // 8 MB
__device__ __nv_bfloat16 g_adjhi[NV * NV];
__device__ __nv_bfloat16 g_adjlo[NV * NV];
__device__ float g_sum[NV * NO];
__device__ float g_sqs[NV * NO];
__device__ float g_s[NV * NO];
__device__ float g_t[NV * NO];

// ---------------------------------------------------------------------------
// Helpers (baseline PTX only)
// ---------------------------------------------------------------------------
__device__ __forceinline__ uint32_t smem_u32(const void* p) {
    uint32_t a;
    asm("{ .reg .u64 t; cvta.to.shared.u64 t, %1; cvt.u32.u64 %0, t; }"
        : "=r"(a) : "l"(p));
    return a;
}
#define SWZ(off) ((uint32_t)(off) ^ ((((uint32_t)(off)) >> 3) & 0x70))  // 128B rows

__device__ __forceinline__ void ldsm_x4(uint32_t* r, uint32_t addr) {
    asm volatile("ldmatrix.sync.aligned.m8n8.x4.shared.b16 {%0,%1,%2,%3}, [%4];"
                 : "=r"(r[0]), "=r"(r[1]), "=r"(r[2]), "=r"(r[3]) : "r"(addr));
}
__device__ __forceinline__ void ldsm_x2(uint32_t* r, uint32_t addr) {
    asm volatile("ldmatrix.sync.aligned.m8n8.x2.shared.b16 {%0,%1}, [%2];"
                 : "=r"(r[0]), "=r"(r[1]) : "r"(addr));
}
__device__ __forceinline__ void ldsm_x2t(uint32_t* r, uint32_t addr) {
    asm volatile("ldmatrix.sync.aligned.m8n8.x2.trans.shared.b16 {%0,%1}, [%2];"
                 : "=r"(r[0]), "=r"(r[1]) : "r"(addr));
}
__device__ __forceinline__ void mma_bf16(float* d, const uint32_t* a,
                                         const uint32_t* b) {
    asm volatile(
        "mma.sync.aligned.m16n8k16.row.col.f32.bf16.bf16.f32 "
        "{%0,%1,%2,%3}, {%4,%5,%6,%7}, {%8,%9}, {%0,%1,%2,%3};"
        : "+f"(d[0]), "+f"(d[1]), "+f"(d[2]), "+f"(d[3])
        : "r"(a[0]), "r"(a[1]), "r"(a[2]), "r"(a[3]), "r"(b[0]), "r"(b[1]));
}
__device__ __forceinline__ void mma_f16(float* d, const uint32_t* a,
                                        const uint32_t* b) {
    asm volatile(
        "mma.sync.aligned.m16n8k16.row.col.f32.f16.f16.f32 "
        "{%0,%1,%2,%3}, {%4,%5,%6,%7}, {%8,%9}, {%0,%1,%2,%3};"
        : "+f"(d[0]), "+f"(d[1]), "+f"(d[2]), "+f"(d[3])
        : "r"(a[0]), "r"(a[1]), "r"(a[2]), "r"(a[3]), "r"(b[0]), "r"(b[1]));
}
__device__ __forceinline__ void cp16(uint32_t smem, const void* g) {
    asm volatile("cp.async.cg.shared.global [%0], [%1], 16;"
                 :: "r"(smem), "l"(g) : "memory");
}
#define CP_COMMIT() asm volatile("cp.async.commit_group;" ::: "memory")
#define CP_WAIT(N)  asm volatile("cp.async.wait_group %0;" :: "n"(N) : "memory")

// ---------------------------------------------------------------------------
// Kernel A: split W into fp16 hi/lo, transposed to K-major [v][o][i]
// ---------------------------------------------------------------------------
__global__ __launch_bounds__(256) void convert_W(const float* __restrict__ W) {
    __shared__ float tile[256][65];
    const int v = blockIdx.y, o0 = blockIdx.x * 64;
    const int t = threadIdx.x;
    const float* src = W + (size_t)v * NI * NO + o0;
#pragma unroll 8
    for (int r = 0; r < 64; r++) {
        int idx = r * 256 + t;
        int i = idx >> 6, o = idx & 63;
        tile[i][o] = src[(size_t)i * NO + o];
    }
    __syncthreads();
    __half* dh = g_Whi + ((size_t)v * NO + o0) * NI;
    __half* dl = g_Wlo + ((size_t)v * NO + o0) * NI;
#pragma unroll 8
    for (int r = 0; r < 64; r++) {
        float x = tile[t][r];
        __half hi = __float2half_rn(x);
        __half lo = __float2half_rn(x - __half2float(hi));
        dh[(size_t)r * NI + t] = hi;
        dl[(size_t)r * NI + t] = lo;
    }
}

// ---------------------------------------------------------------------------
// Kernel A2: split adj into bf16 hi/lo AND zero stats accumulators.
// ---------------------------------------------------------------------------
__global__ void convert_adj(const float* __restrict__ adj) {
    int i = blockIdx.x * 256 + threadIdx.x;   // 0..4095
    float x = adj[i];
    __nv_bfloat16 hi = __float2bfloat16(x);
    g_adjhi[i] = hi;
    g_adjlo[i] = __float2bfloat16(x - __bfloat162float(hi));
    ((float4*)g_sum)[i] = make_float4(0.f, 0.f, 0.f, 0.f);
    ((float4*)g_sqs)[i] = make_float4(0.f, 0.f, 0.f, 0.f);
}

// ---------------------------------------------------------------------------
// Kernel B: R7-structure GEMM, fp16 single-split (A single, W hi+lo): 2 MMAs.
// grid (NB/128, NO/128, NV), block 256 (8 warps), tile 128x128, K-chunk 64.
// smem: A 16KB + Bhi 16KB + Blo 16KB = 48KB -> occ 2.
// ---------------------------------------------------------------------------
static constexpr int A_OFF = 0;
static constexpr int B_HI = 16384;
static constexpr int B_LO = 32768;
static constexpr int GEMM_DSMEM = 49152 + 1024;

__device__ __forceinline__ void load_A_regs(float4* areg,
                                            const float* __restrict__ feat,
                                            int m0, int v, int k0, int t) {
#pragma unroll
    for (int r = 0; r < 8; r++) {
        int idx = t + r * 256;            // 0..2047 float4s (128m x 64k)
        int m = idx >> 4, kq = idx & 15;
        areg[r] = *(const float4*)(feat +
                   ((size_t)(m0 + m) * NV + v) * NI + k0 + kq * 4);
    }
}
__device__ __forceinline__ void store_A_smem(char* buf, const float4* areg,
                                             int t) {
#pragma unroll
    for (int r = 0; r < 8; r++) {
        int idx = t + r * 256;
        int m = idx >> 4, kq = idx & 15;
        float4 x = areg[r];
        __half2 p0 = __floats2half2_rn(x.x, x.y);
        __half2 p1 = __floats2half2_rn(x.z, x.w);
        uint32_t off = SWZ(m * 128 + kq * 8);
        *(uint2*)(buf + A_OFF + off) =
            make_uint2(*(uint32_t*)&p0, *(uint32_t*)&p1);
    }
}
__device__ __forceinline__ void issue_B(uint32_t sb,
                                        const __half* __restrict__ Wh,
                                        const __half* __restrict__ Wl,
                                        int k0, int t) {
#pragma unroll
    for (int r = 0; r < 4; r++) {
        int idx = t + r * 256;            // 0..1023 16B chunks (128n x 64k)
        int n = idx >> 3, kc = idx & 7;
        uint32_t off = SWZ(n * 128 + kc * 16);
        cp16(sb + B_HI + off, Wh + (size_t)n * NI + k0 + kc * 8);
        cp16(sb + B_LO + off, Wl + (size_t)n * NI + k0 + kc * 8);
    }
}

__global__ __launch_bounds__(256, 2) void gemm_mma(const float* __restrict__ feat,
                                                   const float* __restrict__ bias) {
    extern __shared__ char dynraw[];
    uint32_t rawa = smem_u32(dynraw);
    char* smb = dynraw + (((rawa + 1023) & ~1023u) - rawa);
    const uint32_t sb = smem_u32(smb);

    const int v  = blockIdx.z;
    const int m0 = blockIdx.x * 128;
    const int n0 = blockIdx.y * 128;
    const int t  = threadIdx.x;
    const int lane = t & 31;
    const int w = t >> 5;
    const int mw = (w >> 2) * 64;
    const int nw = (w & 3) * 32;

    float acc[4][4][4];
#pragma unroll
    for (int i = 0; i < 4; i++)
#pragma unroll
        for (int j = 0; j < 4; j++)
#pragma unroll
            for (int q = 0; q < 4; q++) acc[i][j][q] = 0.f;

    const __half* Wh = g_Whi + ((size_t)v * NO + n0) * NI;
    const __half* Wl = g_Wlo + ((size_t)v * NO + n0) * NI;

    float4 areg[8];
    load_A_regs(areg, feat, m0, v, 0, t);

#pragma unroll
    for (int c = 0; c < 4; c++) {
        if (c) __syncthreads();            // prev chunk consumers done
        issue_B(sb, Wh, Wl, c * 64, t);    // cp.async into the single stage
        CP_COMMIT();
        store_A_smem(smb, areg, t);        // cvt+STS overlaps cp.async
        if (c < 3) load_A_regs(areg, feat, m0, v, (c + 1) * 64, t);  // prefetch
        CP_WAIT(0);
        __syncthreads();

#pragma unroll
        for (int ks = 0; ks < 4; ks++) {
            uint32_t bh[4][2], bl[4][2];
            {
                int brow = nw + (lane & 7);
                int bk = ks * 16 + ((lane >> 3) & 1) * 8;
#pragma unroll
                for (int nt = 0; nt < 4; nt++) {
                    uint32_t addr = sb + B_HI + SWZ((brow + nt * 8) * 128 + bk * 2);
                    ldsm_x2(bh[nt], addr);
                    ldsm_x2(bl[nt], addr + (B_LO - B_HI));
                }
            }
            int arow = mw + (lane & 7) + ((lane >> 3) & 1) * 8;
            int ak = ks * 16 + ((lane >> 4) & 1) * 8;
#pragma unroll
            for (int mt = 0; mt < 4; mt++) {
                uint32_t ra[4];
                ldsm_x4(ra, sb + A_OFF + SWZ((arow + mt * 16) * 128 + ak * 2));
#pragma unroll
                for (int nt = 0; nt < 4; nt++) {
                    mma_f16(acc[mt][nt], ra, bh[nt]);
                    mma_f16(acc[mt][nt], ra, bl[nt]);
                }
            }
        }
    }

    // ---- epilogue: bias + store h + shuffle-reduced column stats
#pragma unroll
    for (int nt = 0; nt < 4; nt++) {
        const int nl = nw + nt * 8 + (lane & 3) * 2;   // col in block tile
        const int n = n0 + nl;
        float2 bv = *(const float2*)(bias + v * NO + n);
        float2 sum2 = make_float2(0.f, 0.f), sq2 = make_float2(0.f, 0.f);
#pragma unroll
        for (int mt = 0; mt < 4; mt++) {
            int mlo = m0 + mw + mt * 16 + (lane >> 2);
            float2 o0, o1;
            o0.x = acc[mt][nt][0] + bv.x;
            o0.y = acc[mt][nt][1] + bv.y;
            o1.x = acc[mt][nt][2] + bv.x;
            o1.y = acc[mt][nt][3] + bv.y;
            *(float2*)(g_h + (size_t)mlo * (NV * NO) + v * NO + n) = o0;
            *(float2*)(g_h + (size_t)(mlo + 8) * (NV * NO) + v * NO + n) = o1;
            sum2.x += o0.x + o1.x;
            sum2.y += o0.y + o1.y;
            sq2.x += fmaf(o0.x, o0.x, o1.x * o1.x);
            sq2.y += fmaf(o0.y, o0.y, o1.y * o1.y);
        }
#pragma unroll
        for (int msk = 4; msk <= 16; msk <<= 1) {
            sum2.x += __shfl_xor_sync(0xffffffffu, sum2.x, msk);
            sum2.y += __shfl_xor_sync(0xffffffffu, sum2.y, msk);
            sq2.x  += __shfl_xor_sync(0xffffffffu, sq2.x, msk);
            sq2.y  += __shfl_xor_sync(0xffffffffu, sq2.y, msk);
        }
        if (lane < 4) {
            atomicAdd(&g_sum[v * NO + n],     sum2.x);
            atomicAdd(&g_sum[v * NO + n + 1], sum2.y);
            atomicAdd(&g_sqs[v * NO + n],     sq2.x);
            atomicAdd(&g_sqs[v * NO + n + 1], sq2.y);
        }
    }
}

// ---------------------------------------------------------------------------
// Kernel C: finalize BN fold
// ---------------------------------------------------------------------------
__global__ __launch_bounds__(256) void stats_fin(const float* __restrict__ gamma,
                                                 const float* __restrict__ beta) {
    const int col = blockIdx.x * 256 + threadIdx.x;
    float mean = g_sum[col] * (1.f / NB);
    float var  = g_sqs[col] * (1.f / NB) - mean * mean;
    float s    = gamma[col] * rsqrtf(var + EPS);
    g_s[col] = s;
    g_t[col] = fmaf(-mean, s, beta[col]);
}

// ---------------------------------------------------------------------------
// Kernel D: tensorized mix (unchanged from the proven 28us version)
// ---------------------------------------------------------------------------
static constexpr int OPAD = 264;
static constexpr int HS_HI = 0;
static constexpr int HS_LO = 33792;
static constexpr int ADJ_HI = 67584;
static constexpr int ADJ_LO = 76800;
static constexpr int MIX_DSMEM = 86016 + 1024;

__global__ __launch_bounds__(256, 2) void mix_tc(float* __restrict__ out) {
    extern __shared__ char dynraw[];
    uint32_t rawa = smem_u32(dynraw);
    char* smb = dynraw + (((rawa + 1023) & ~1023u) - rawa);
    const uint32_t sbase = smem_u32(smb);

    const int b = blockIdx.x;
    const int t = threadIdx.x;
    const int lane = t & 31;
    const int w = t >> 5;

    const float4* h4 = (const float4*)(g_h + (size_t)b * NV * NO);
    const float4* s4 = (const float4*)g_s;
    const float4* t4 = (const float4*)g_t;
#pragma unroll
    for (int r = 0; r < 16; r++) {
        int idx = t + r * 256;
        int v = idx >> 6, oq = idx & 63;
        float4 h = h4[idx], sv = s4[idx], tv = t4[idx];
        float x0 = fmaf(h.x, sv.x, tv.x);
        float x1 = fmaf(h.y, sv.y, tv.y);
        float x2 = fmaf(h.z, sv.z, tv.z);
        float x3 = fmaf(h.w, sv.w, tv.w);
        __nv_bfloat16 h0 = __float2bfloat16(x0);
        __nv_bfloat16 h1 = __float2bfloat16(x1);
        __nv_bfloat16 h2 = __float2bfloat16(x2);
        __nv_bfloat16 h3 = __float2bfloat16(x3);
        __nv_bfloat16 l0 = __float2bfloat16(x0 - __bfloat162float(h0));
        __nv_bfloat16 l1 = __float2bfloat16(x1 - __bfloat162float(h1));
        __nv_bfloat16 l2 = __float2bfloat16(x2 - __bfloat162float(h2));
        __nv_bfloat16 l3 = __float2bfloat16(x3 - __bfloat162float(h3));
        __nv_bfloat162 hp0 = {h0, h1}, hp1 = {h2, h3};
        __nv_bfloat162 lp0 = {l0, l1}, lp1 = {l2, l3};
        uint32_t off = (uint32_t)(v * (OPAD * 2) + oq * 8);
        *(uint2*)(smb + HS_HI + off) =
            make_uint2(*(uint32_t*)&hp0, *(uint32_t*)&hp1);
        *(uint2*)(smb + HS_LO + off) =
            make_uint2(*(uint32_t*)&lp0, *(uint32_t*)&lp1);
    }
#pragma unroll
    for (int r = 0; r < 8; r++) {
        int idx = t + r * 256;
        int u = idx >> 5, q = idx & 31;
        *(uint32_t*)(smb + ADJ_HI + u * 144 + q * 4) =
            ((const uint32_t*)g_adjhi)[idx];
        *(uint32_t*)(smb + ADJ_LO + u * 144 + q * 4) =
            ((const uint32_t*)g_adjlo)[idx];
    }
    __syncthreads();

    const int mw = (w >> 1) * 16;
    const int nw = (w & 1) * 128;

    float acc[16][4];
#pragma unroll
    for (int i = 0; i < 16; i++)
#pragma unroll
        for (int q = 0; q < 4; q++) acc[i][q] = 0.f;

#pragma unroll
    for (int ks = 0; ks < 4; ks++) {
        uint32_t ah[4], al[4];
        uint32_t aaddr = sbase + ADJ_HI + (mw + (lane & 15)) * 144 +
                         (ks * 16 + (lane >> 4) * 8) * 2;
        ldsm_x4(ah, aaddr);
        ldsm_x4(al, aaddr + (ADJ_LO - ADJ_HI));

        uint32_t brow = sbase + HS_HI + (ks * 16 + (lane & 15)) * (OPAD * 2);
#pragma unroll
        for (int nt = 0; nt < 16; nt++) {
            int n0 = nw + nt * 8;
            uint32_t bh[2], bl[2];
            ldsm_x2t(bh, brow + n0 * 2);
            ldsm_x2t(bl, brow + n0 * 2 + (HS_LO - HS_HI));
            mma_bf16(acc[nt], ah, bh);
            mma_bf16(acc[nt], ah, bl);
            mma_bf16(acc[nt], al, bh);
        }
    }

    float* ob = out + (size_t)b * NV * NO;
    const int u0 = mw + (lane >> 2);
#pragma unroll
    for (int nt = 0; nt < 16; nt++) {
        int o = nw + nt * 8 + (lane & 3) * 2;
        float2 r0, r1;
        r0.x = fmaxf(acc[nt][0], 0.f);
        r0.y = fmaxf(acc[nt][1], 0.f);
        r1.x = fmaxf(acc[nt][2], 0.f);
        r1.y = fmaxf(acc[nt][3], 0.f);
        *(float2*)(ob + (size_t)u0 * NO + o) = r0;
        *(float2*)(ob + (size_t)(u0 + 8) * NO + o) = r1;
    }
}

// ---------------------------------------------------------------------------
extern "C" void kernel_launch(void* const* d_in, const int* in_sizes, int n_in,
                              void* d_out, int out_size) {
    const float* feat  = (const float*)d_in[0];
    const float* adj   = (const float*)d_in[1];
    const float* W     = (const float*)d_in[2];
    const float* bias  = (const float*)d_in[3];
    const float* gamma = (const float*)d_in[4];
    const float* beta  = (const float*)d_in[5];
    float* out = (float*)d_out;

    cudaFuncSetAttribute(gemm_mma, cudaFuncAttributeMaxDynamicSharedMemorySize,
                         GEMM_DSMEM);
    cudaFuncSetAttribute(mix_tc, cudaFuncAttributeMaxDynamicSharedMemorySize,
                         MIX_DSMEM);

    convert_W<<<dim3(NO / 64, NV), 256>>>(W);
    convert_adj<<<16, 256>>>(adj);   // also zeroes g_sum/g_sqs
    gemm_mma<<<dim3(NB / 128, NO / 128, NV), 256, GEMM_DSMEM>>>(feat, bias);
    stats_fin<<<64, 256>>>(gamma, beta);
    mix_tc<<<NB, 256, MIX_DSMEM>>>(out);
}

// round 11
// speedup vs baseline: 1.2677x; 1.0319x over previous
#include <cuda_runtime.h>
#include <cuda_bf16.h>
#include <cuda_fp16.h>
#include <cstdint>

#define NB 1024
#define NV 64
#define NI 256
#define NO 256
constexpr float EPS = 1e-5f;

// ---------------------------------------------------------------------------
// Device scratch
// ---------------------------------------------------------------------------
__device__ __half g_h16[(size_t)NB * NV * NO];         // 32 MB: h (fp16)
__device__ __half g_Whi[(size_t)NV * NO * NI];         // 8 MB, layout [v][o][i]
__device__ __half g_Wlo[(size_t)NV * NO * NI];         // 8 MB
__device__ __half g_adj16[NV * NV];
__device__ float g_sum[NV * NO];
__device__ float g_sqs[NV * NO];
__device__ float g_s[NV * NO];
__device__ float g_t[NV * NO];

// ---------------------------------------------------------------------------
// Helpers (baseline PTX only)
// ---------------------------------------------------------------------------
__device__ __forceinline__ uint32_t smem_u32(const void* p) {
    uint32_t a;
    asm("{ .reg .u64 t; cvta.to.shared.u64 t, %1; cvt.u32.u64 %0, t; }"
        : "=r"(a) : "l"(p));
    return a;
}
#define SWZ(off) ((uint32_t)(off) ^ ((((uint32_t)(off)) >> 3) & 0x70))  // 128B rows

__device__ __forceinline__ void ldsm_x4(uint32_t* r, uint32_t addr) {
    asm volatile("ldmatrix.sync.aligned.m8n8.x4.shared.b16 {%0,%1,%2,%3}, [%4];"
                 : "=r"(r[0]), "=r"(r[1]), "=r"(r[2]), "=r"(r[3]) : "r"(addr));
}
__device__ __forceinline__ void ldsm_x2(uint32_t* r, uint32_t addr) {
    asm volatile("ldmatrix.sync.aligned.m8n8.x2.shared.b16 {%0,%1}, [%2];"
                 : "=r"(r[0]), "=r"(r[1]) : "r"(addr));
}
__device__ __forceinline__ void ldsm_x2t(uint32_t* r, uint32_t addr) {
    asm volatile("ldmatrix.sync.aligned.m8n8.x2.trans.shared.b16 {%0,%1}, [%2];"
                 : "=r"(r[0]), "=r"(r[1]) : "r"(addr));
}
__device__ __forceinline__ void mma_f16(float* d, const uint32_t* a,
                                        const uint32_t* b) {
    asm volatile(
        "mma.sync.aligned.m16n8k16.row.col.f32.f16.f16.f32 "
        "{%0,%1,%2,%3}, {%4,%5,%6,%7}, {%8,%9}, {%0,%1,%2,%3};"
        : "+f"(d[0]), "+f"(d[1]), "+f"(d[2]), "+f"(d[3])
        : "r"(a[0]), "r"(a[1]), "r"(a[2]), "r"(a[3]), "r"(b[0]), "r"(b[1]));
}
__device__ __forceinline__ void cp16(uint32_t smem, const void* g) {
    asm volatile("cp.async.cg.shared.global [%0], [%1], 16;"
                 :: "r"(smem), "l"(g) : "memory");
}
#define CP_COMMIT() asm volatile("cp.async.commit_group;" ::: "memory")
#define CP_WAIT(N)  asm volatile("cp.async.wait_group %0;" :: "n"(N) : "memory")

// ---------------------------------------------------------------------------
// Kernel A: split W into fp16 hi/lo, transposed to K-major [v][o][i]
// ---------------------------------------------------------------------------
__global__ __launch_bounds__(256) void convert_W(const float* __restrict__ W) {
    __shared__ float tile[256][65];
    const int v = blockIdx.y, o0 = blockIdx.x * 64;
    const int t = threadIdx.x;
    const float* src = W + (size_t)v * NI * NO + o0;
#pragma unroll 8
    for (int r = 0; r < 64; r++) {
        int idx = r * 256 + t;
        int i = idx >> 6, o = idx & 63;
        tile[i][o] = src[(size_t)i * NO + o];
    }
    __syncthreads();
    __half* dh = g_Whi + ((size_t)v * NO + o0) * NI;
    __half* dl = g_Wlo + ((size_t)v * NO + o0) * NI;
#pragma unroll 8
    for (int r = 0; r < 64; r++) {
        float x = tile[t][r];
        __half hi = __float2half_rn(x);
        __half lo = __float2half_rn(x - __half2float(hi));
        dh[(size_t)r * NI + t] = hi;
        dl[(size_t)r * NI + t] = lo;
    }
}

// ---------------------------------------------------------------------------
// Kernel A2: adj -> fp16 AND zero stats accumulators. grid 16 x 256.
// ---------------------------------------------------------------------------
__global__ void convert_adj(const float* __restrict__ adj) {
    int i = blockIdx.x * 256 + threadIdx.x;   // 0..4095
    g_adj16[i] = __float2half_rn(adj[i]);
    ((float4*)g_sum)[i] = make_float4(0.f, 0.f, 0.f, 0.f);
    ((float4*)g_sqs)[i] = make_float4(0.f, 0.f, 0.f, 0.f);
}

// ---------------------------------------------------------------------------
// Kernel B: R7-structure GEMM, fp16 single-A + split-W: 2 MMAs per k-step.
// grid (NB/128, NO/128, NV), block 256 (8 warps), tile 128x128, K-chunk 64.
// h stored as fp16. smem: A 16KB + Bhi 16KB + Blo 16KB = 48KB -> occ 2.
// ---------------------------------------------------------------------------
static constexpr int A_OFF = 0;
static constexpr int B_HI = 16384;
static constexpr int B_LO = 32768;
static constexpr int GEMM_DSMEM = 49152 + 1024;

__device__ __forceinline__ void load_A_regs(float4* areg,
                                            const float* __restrict__ feat,
                                            int m0, int v, int k0, int t) {
#pragma unroll
    for (int r = 0; r < 8; r++) {
        int idx = t + r * 256;            // 0..2047 float4s (128m x 64k)
        int m = idx >> 4, kq = idx & 15;
        areg[r] = *(const float4*)(feat +
                   ((size_t)(m0 + m) * NV + v) * NI + k0 + kq * 4);
    }
}
__device__ __forceinline__ void store_A_smem(char* buf, const float4* areg,
                                             int t) {
#pragma unroll
    for (int r = 0; r < 8; r++) {
        int idx = t + r * 256;
        int m = idx >> 4, kq = idx & 15;
        float4 x = areg[r];
        __half2 p0 = __floats2half2_rn(x.x, x.y);
        __half2 p1 = __floats2half2_rn(x.z, x.w);
        uint32_t off = SWZ(m * 128 + kq * 8);
        *(uint2*)(buf + A_OFF + off) =
            make_uint2(*(uint32_t*)&p0, *(uint32_t*)&p1);
    }
}
__device__ __forceinline__ void issue_B(uint32_t sb,
                                        const __half* __restrict__ Wh,
                                        const __half* __restrict__ Wl,
                                        int k0, int t) {
#pragma unroll
    for (int r = 0; r < 4; r++) {
        int idx = t + r * 256;            // 0..1023 16B chunks (128n x 64k)
        int n = idx >> 3, kc = idx & 7;
        uint32_t off = SWZ(n * 128 + kc * 16);
        cp16(sb + B_HI + off, Wh + (size_t)n * NI + k0 + kc * 8);
        cp16(sb + B_LO + off, Wl + (size_t)n * NI + k0 + kc * 8);
    }
}

__global__ __launch_bounds__(256, 2) void gemm_mma(const float* __restrict__ feat,
                                                   const float* __restrict__ bias) {
    extern __shared__ char dynraw[];
    uint32_t rawa = smem_u32(dynraw);
    char* smb = dynraw + (((rawa + 1023) & ~1023u) - rawa);
    const uint32_t sb = smem_u32(smb);

    const int v  = blockIdx.z;
    const int m0 = blockIdx.x * 128;
    const int n0 = blockIdx.y * 128;
    const int t  = threadIdx.x;
    const int lane = t & 31;
    const int w = t >> 5;
    const int mw = (w >> 2) * 64;
    const int nw = (w & 3) * 32;

    float acc[4][4][4];
#pragma unroll
    for (int i = 0; i < 4; i++)
#pragma unroll
        for (int j = 0; j < 4; j++)
#pragma unroll
            for (int q = 0; q < 4; q++) acc[i][j][q] = 0.f;

    const __half* Wh = g_Whi + ((size_t)v * NO + n0) * NI;
    const __half* Wl = g_Wlo + ((size_t)v * NO + n0) * NI;

    float4 areg[8];
    load_A_regs(areg, feat, m0, v, 0, t);

#pragma unroll
    for (int c = 0; c < 4; c++) {
        if (c) __syncthreads();            // prev chunk consumers done
        issue_B(sb, Wh, Wl, c * 64, t);    // cp.async into the single stage
        CP_COMMIT();
        store_A_smem(smb, areg, t);        // cvt+STS overlaps cp.async
        if (c < 3) load_A_regs(areg, feat, m0, v, (c + 1) * 64, t);  // prefetch
        CP_WAIT(0);
        __syncthreads();

#pragma unroll
        for (int ks = 0; ks < 4; ks++) {
            uint32_t bh[4][2], bl[4][2];
            {
                int brow = nw + (lane & 7);
                int bk = ks * 16 + ((lane >> 3) & 1) * 8;
#pragma unroll
                for (int nt = 0; nt < 4; nt++) {
                    uint32_t addr = sb + B_HI + SWZ((brow + nt * 8) * 128 + bk * 2);
                    ldsm_x2(bh[nt], addr);
                    ldsm_x2(bl[nt], addr + (B_LO - B_HI));
                }
            }
            int arow = mw + (lane & 7) + ((lane >> 3) & 1) * 8;
            int ak = ks * 16 + ((lane >> 4) & 1) * 8;
#pragma unroll
            for (int mt = 0; mt < 4; mt++) {
                uint32_t ra[4];
                ldsm_x4(ra, sb + A_OFF + SWZ((arow + mt * 16) * 128 + ak * 2));
#pragma unroll
                for (int nt = 0; nt < 4; nt++) {
                    mma_f16(acc[mt][nt], ra, bh[nt]);
                    mma_f16(acc[mt][nt], ra, bl[nt]);
                }
            }
        }
    }

    // ---- epilogue: bias + store h (fp16) + shuffle-reduced column stats
#pragma unroll
    for (int nt = 0; nt < 4; nt++) {
        const int nl = nw + nt * 8 + (lane & 3) * 2;   // col in block tile (even)
        const int n = n0 + nl;
        float2 bv = *(const float2*)(bias + v * NO + n);
        float2 sum2 = make_float2(0.f, 0.f), sq2 = make_float2(0.f, 0.f);
#pragma unroll
        for (int mt = 0; mt < 4; mt++) {
            int mlo = m0 + mw + mt * 16 + (lane >> 2);
            float2 o0, o1;
            o0.x = acc[mt][nt][0] + bv.x;
            o0.y = acc[mt][nt][1] + bv.y;
            o1.x = acc[mt][nt][2] + bv.x;
            o1.y = acc[mt][nt][3] + bv.y;
            __half2 p0 = __floats2half2_rn(o0.x, o0.y);
            __half2 p1 = __floats2half2_rn(o1.x, o1.y);
            *(uint32_t*)(g_h16 + (size_t)mlo * (NV * NO) + v * NO + n) =
                *(uint32_t*)&p0;
            *(uint32_t*)(g_h16 + (size_t)(mlo + 8) * (NV * NO) + v * NO + n) =
                *(uint32_t*)&p1;
            sum2.x += o0.x + o1.x;
            sum2.y += o0.y + o1.y;
            sq2.x += fmaf(o0.x, o0.x, o1.x * o1.x);
            sq2.y += fmaf(o0.y, o0.y, o1.y * o1.y);
        }
#pragma unroll
        for (int msk = 4; msk <= 16; msk <<= 1) {
            sum2.x += __shfl_xor_sync(0xffffffffu, sum2.x, msk);
            sum2.y += __shfl_xor_sync(0xffffffffu, sum2.y, msk);
            sq2.x  += __shfl_xor_sync(0xffffffffu, sq2.x, msk);
            sq2.y  += __shfl_xor_sync(0xffffffffu, sq2.y, msk);
        }
        if (lane < 4) {
            atomicAdd(&g_sum[v * NO + n],     sum2.x);
            atomicAdd(&g_sum[v * NO + n + 1], sum2.y);
            atomicAdd(&g_sqs[v * NO + n],     sq2.x);
            atomicAdd(&g_sqs[v * NO + n + 1], sq2.y);
        }
    }
}

// ---------------------------------------------------------------------------
// Kernel C: finalize BN fold
// ---------------------------------------------------------------------------
__global__ __launch_bounds__(256) void stats_fin(const float* __restrict__ gamma,
                                                 const float* __restrict__ beta) {
    const int col = blockIdx.x * 256 + threadIdx.x;
    float mean = g_sum[col] * (1.f / NB);
    float var  = g_sqs[col] * (1.f / NB) - mean * mean;
    float s    = gamma[col] * rsqrtf(var + EPS);
    g_s[col] = s;
    g_t[col] = fmaf(-mean, s, beta[col]);
}

// ---------------------------------------------------------------------------
// Kernel D: tensorized mix, fp16 2-term: adj single, hs = s*h+t split hi/lo.
// out[b,u,o] = relu( sum_v adj[u,v] * hs[v,o] )
// ---------------------------------------------------------------------------
static constexpr int OPAD = 264;                 // hs row stride (fp16 elems)
static constexpr int HS_HI = 0;                  // 64*264*2 = 33792 B
static constexpr int HS_LO = 33792;
static constexpr int ADJ_OFF = 67584;            // 64 rows x 72 elems x 2B
static constexpr int MIX_DSMEM = 76800 + 1024;

__global__ __launch_bounds__(256, 2) void mix_tc(float* __restrict__ out) {
    extern __shared__ char dynraw[];
    uint32_t rawa = smem_u32(dynraw);
    char* smb = dynraw + (((rawa + 1023) & ~1023u) - rawa);
    const uint32_t sbase = smem_u32(smb);

    const int b = blockIdx.x;
    const int t = threadIdx.x;
    const int lane = t & 31;
    const int w = t >> 5;

    // ---- stage hs = s*h + t (from fp16 h), split fp16 hi/lo, [v][OPAD]
    const uint2*  h2 = (const uint2*)(g_h16 + (size_t)b * NV * NO);  // 4 halves
    const float4* s4 = (const float4*)g_s;
    const float4* t4 = (const float4*)g_t;
#pragma unroll
    for (int r = 0; r < 16; r++) {
        int idx = t + r * 256;            // 0..4095 (4 elems each)
        int v = idx >> 6, oq = idx & 63;
        uint2 hp = h2[idx];
        __half2 ha = *(__half2*)&hp.x, hb = *(__half2*)&hp.y;
        float4 sv = s4[idx], tv = t4[idx];
        float x0 = fmaf(__half2float(ha.x), sv.x, tv.x);
        float x1 = fmaf(__half2float(ha.y), sv.y, tv.y);
        float x2 = fmaf(__half2float(hb.x), sv.z, tv.z);
        float x3 = fmaf(__half2float(hb.y), sv.w, tv.w);
        __half h0 = __float2half_rn(x0);
        __half h1 = __float2half_rn(x1);
        __half h2c = __float2half_rn(x2);
        __half h3 = __float2half_rn(x3);
        __half l0 = __float2half_rn(x0 - __half2float(h0));
        __half l1 = __float2half_rn(x1 - __half2float(h1));
        __half l2 = __float2half_rn(x2 - __half2float(h2c));
        __half l3 = __float2half_rn(x3 - __half2float(h3));
        __half2 hp0 = {h0, h1}, hp1 = {h2c, h3};
        __half2 lp0 = {l0, l1}, lp1 = {l2, l3};
        uint32_t off = (uint32_t)(v * (OPAD * 2) + oq * 8);
        *(uint2*)(smb + HS_HI + off) =
            make_uint2(*(uint32_t*)&hp0, *(uint32_t*)&hp1);
        *(uint2*)(smb + HS_LO + off) =
            make_uint2(*(uint32_t*)&lp0, *(uint32_t*)&lp1);
    }
    // ---- stage adj (single fp16), [u][72] rows
#pragma unroll
    for (int r = 0; r < 8; r++) {
        int idx = t + r * 256;            // 0..2047 uint32s (2 fp16 each)
        int u = idx >> 5, q = idx & 31;
        *(uint32_t*)(smb + ADJ_OFF + u * 144 + q * 4) =
            ((const uint32_t*)g_adj16)[idx];
    }
    __syncthreads();

    const int mw = (w >> 1) * 16;     // u tile (4 tiles of 16)
    const int nw = (w & 1) * 128;     // o half

    float acc[16][4];
#pragma unroll
    for (int i = 0; i < 16; i++)
#pragma unroll
        for (int q = 0; q < 4; q++) acc[i][q] = 0.f;

#pragma unroll
    for (int ks = 0; ks < 4; ks++) {
        uint32_t ah[4];
        uint32_t aaddr = sbase + ADJ_OFF + (mw + (lane & 15)) * 144 +
                         (ks * 16 + (lane >> 4) * 8) * 2;
        ldsm_x4(ah, aaddr);

        uint32_t brow = sbase + HS_HI + (ks * 16 + (lane & 15)) * (OPAD * 2);
#pragma unroll
        for (int nt = 0; nt < 16; nt++) {
            int n0 = nw + nt * 8;
            uint32_t bh[2], bl[2];
            ldsm_x2t(bh, brow + n0 * 2);
            ldsm_x2t(bl, brow + n0 * 2 + (HS_LO - HS_HI));
            mma_f16(acc[nt], ah, bh);
            mma_f16(acc[nt], ah, bl);
        }
    }

    // ---- epilogue: relu + store
    float* ob = out + (size_t)b * NV * NO;
    const int u0 = mw + (lane >> 2);
#pragma unroll
    for (int nt = 0; nt < 16; nt++) {
        int o = nw + nt * 8 + (lane & 3) * 2;
        float2 r0, r1;
        r0.x = fmaxf(acc[nt][0], 0.f);
        r0.y = fmaxf(acc[nt][1], 0.f);
        r1.x = fmaxf(acc[nt][2], 0.f);
        r1.y = fmaxf(acc[nt][3], 0.f);
        *(float2*)(ob + (size_t)u0 * NO + o) = r0;
        *(float2*)(ob + (size_t)(u0 + 8) * NO + o) = r1;
    }
}

// ---------------------------------------------------------------------------
extern "C" void kernel_launch(void* const* d_in, const int* in_sizes, int n_in,
                              void* d_out, int out_size) {
    const float* feat  = (const float*)d_in[0];
    const float* adj   = (const float*)d_in[1];
    const float* W     = (const float*)d_in[2];
    const float* bias  = (const float*)d_in[3];
    const float* gamma = (const float*)d_in[4];
    const float* beta  = (const float*)d_in[5];
    float* out = (float*)d_out;

    cudaFuncSetAttribute(gemm_mma, cudaFuncAttributeMaxDynamicSharedMemorySize,
                         GEMM_DSMEM);
    cudaFuncSetAttribute(mix_tc, cudaFuncAttributeMaxDynamicSharedMemorySize,
                         MIX_DSMEM);

    convert_W<<<dim3(NO / 64, NV), 256>>>(W);
    convert_adj<<<16, 256>>>(adj);   // also zeroes g_sum/g_sqs
    gemm_mma<<<dim3(NB / 128, NO / 128, NV), 256, GEMM_DSMEM>>>(feat, bias);
    stats_fin<<<64, 256>>>(gamma, beta);
    mix_tc<<<NB, 256, MIX_DSMEM>>>(out);
}

// round 12
// speedup vs baseline: 1.2747x; 1.0056x over previous
#include <cuda_runtime.h>
#include <cuda_bf16.h>
#include <cuda_fp16.h>
#include <cstdint>

#define NB 1024
#define NV 64
#define NI 256
#define NO 256
constexpr float EPS = 1e-5f;

// ---------------------------------------------------------------------------
// Device scratch
// ---------------------------------------------------------------------------
__device__ __half g_h16[(size_t)NB * NV * NO];         // 32 MB: h (fp16)
__device__ __half g_Whi[(size_t)NV * NO * NI];         // 8 MB, layout [v][o][i]
__device__ __half g_Wlo[(size_t)NV * NO * NI];         // 8 MB
__device__ __half g_adj16[NV * NV];
__device__ float g_sum[NV * NO];
__device__ float g_sqs[NV * NO];
__device__ float g_s[NV * NO];
__device__ float g_t[NV * NO];

// ---------------------------------------------------------------------------
// Helpers (baseline PTX only)
// ---------------------------------------------------------------------------
__device__ __forceinline__ uint32_t smem_u32(const void* p) {
    uint32_t a;
    asm("{ .reg .u64 t; cvta.to.shared.u64 t, %1; cvt.u32.u64 %0, t; }"
        : "=r"(a) : "l"(p));
    return a;
}
#define SWZ(off) ((uint32_t)(off) ^ ((((uint32_t)(off)) >> 3) & 0x70))  // 128B rows

__device__ __forceinline__ void ldsm_x4(uint32_t* r, uint32_t addr) {
    asm volatile("ldmatrix.sync.aligned.m8n8.x4.shared.b16 {%0,%1,%2,%3}, [%4];"
                 : "=r"(r[0]), "=r"(r[1]), "=r"(r[2]), "=r"(r[3]) : "r"(addr));
}
__device__ __forceinline__ void ldsm_x2(uint32_t* r, uint32_t addr) {
    asm volatile("ldmatrix.sync.aligned.m8n8.x2.shared.b16 {%0,%1}, [%2];"
                 : "=r"(r[0]), "=r"(r[1]) : "r"(addr));
}
__device__ __forceinline__ void ldsm_x2t(uint32_t* r, uint32_t addr) {
    asm volatile("ldmatrix.sync.aligned.m8n8.x2.trans.shared.b16 {%0,%1}, [%2];"
                 : "=r"(r[0]), "=r"(r[1]) : "r"(addr));
}
__device__ __forceinline__ void mma_f16(float* d, const uint32_t* a,
                                        const uint32_t* b) {
    asm volatile(
        "mma.sync.aligned.m16n8k16.row.col.f32.f16.f16.f32 "
        "{%0,%1,%2,%3}, {%4,%5,%6,%7}, {%8,%9}, {%0,%1,%2,%3};"
        : "+f"(d[0]), "+f"(d[1]), "+f"(d[2]), "+f"(d[3])
        : "r"(a[0]), "r"(a[1]), "r"(a[2]), "r"(a[3]), "r"(b[0]), "r"(b[1]));
}
__device__ __forceinline__ void cp16(uint32_t smem, const void* g) {
    asm volatile("cp.async.cg.shared.global [%0], [%1], 16;"
                 :: "r"(smem), "l"(g) : "memory");
}
#define CP_COMMIT() asm volatile("cp.async.commit_group;" ::: "memory")
#define CP_WAIT(N)  asm volatile("cp.async.wait_group %0;" :: "n"(N) : "memory")

// ---------------------------------------------------------------------------
// Kernel A: split W into fp16 hi/lo, transposed to K-major [v][o][i]
// ---------------------------------------------------------------------------
__global__ __launch_bounds__(256) void convert_W(const float* __restrict__ W) {
    __shared__ float tile[256][65];
    const int v = blockIdx.y, o0 = blockIdx.x * 64;
    const int t = threadIdx.x;
    const float* src = W + (size_t)v * NI * NO + o0;
#pragma unroll 8
    for (int r = 0; r < 64; r++) {
        int idx = r * 256 + t;
        int i = idx >> 6, o = idx & 63;
        tile[i][o] = src[(size_t)i * NO + o];
    }
    __syncthreads();
    __half* dh = g_Whi + ((size_t)v * NO + o0) * NI;
    __half* dl = g_Wlo + ((size_t)v * NO + o0) * NI;
#pragma unroll 8
    for (int r = 0; r < 64; r++) {
        float x = tile[t][r];
        __half hi = __float2half_rn(x);
        __half lo = __float2half_rn(x - __half2float(hi));
        dh[(size_t)r * NI + t] = hi;
        dl[(size_t)r * NI + t] = lo;
    }
}

// ---------------------------------------------------------------------------
// Kernel A2: adj -> fp16 AND zero stats accumulators. grid 16 x 256.
// ---------------------------------------------------------------------------
__global__ void convert_adj(const float* __restrict__ adj) {
    int i = blockIdx.x * 256 + threadIdx.x;   // 0..4095
    g_adj16[i] = __float2half_rn(adj[i]);
    ((float4*)g_sum)[i] = make_float4(0.f, 0.f, 0.f, 0.f);
    ((float4*)g_sqs)[i] = make_float4(0.f, 0.f, 0.f, 0.f);
}

// ---------------------------------------------------------------------------
// Kernel B: R7-structure GEMM, fp16 single-A + split-W: 2 MMAs per k-step.
// grid (NB/128, NO/128, NV), block 256 (8 warps), tile 128x128, K-chunk 64.
// h stored as fp16. smem: A 16KB + Bhi 16KB + Blo 16KB = 48KB -> occ 2.
// ---------------------------------------------------------------------------
static constexpr int A_OFF = 0;
static constexpr int B_HI = 16384;
static constexpr int B_LO = 32768;
static constexpr int GEMM_DSMEM = 49152 + 1024;

__device__ __forceinline__ void load_A_regs(float4* areg,
                                            const float* __restrict__ feat,
                                            int m0, int v, int k0, int t) {
#pragma unroll
    for (int r = 0; r < 8; r++) {
        int idx = t + r * 256;            // 0..2047 float4s (128m x 64k)
        int m = idx >> 4, kq = idx & 15;
        areg[r] = *(const float4*)(feat +
                   ((size_t)(m0 + m) * NV + v) * NI + k0 + kq * 4);
    }
}
__device__ __forceinline__ void store_A_smem(char* buf, const float4* areg,
                                             int t) {
#pragma unroll
    for (int r = 0; r < 8; r++) {
        int idx = t + r * 256;
        int m = idx >> 4, kq = idx & 15;
        float4 x = areg[r];
        __half2 p0 = __floats2half2_rn(x.x, x.y);
        __half2 p1 = __floats2half2_rn(x.z, x.w);
        uint32_t off = SWZ(m * 128 + kq * 8);
        *(uint2*)(buf + A_OFF + off) =
            make_uint2(*(uint32_t*)&p0, *(uint32_t*)&p1);
    }
}
__device__ __forceinline__ void issue_B(uint32_t sb,
                                        const __half* __restrict__ Wh,
                                        const __half* __restrict__ Wl,
                                        int k0, int t) {
#pragma unroll
    for (int r = 0; r < 4; r++) {
        int idx = t + r * 256;            // 0..1023 16B chunks (128n x 64k)
        int n = idx >> 3, kc = idx & 7;
        uint32_t off = SWZ(n * 128 + kc * 16);
        cp16(sb + B_HI + off, Wh + (size_t)n * NI + k0 + kc * 8);
        cp16(sb + B_LO + off, Wl + (size_t)n * NI + k0 + kc * 8);
    }
}

__global__ __launch_bounds__(256, 2) void gemm_mma(const float* __restrict__ feat,
                                                   const float* __restrict__ bias) {
    extern __shared__ char dynraw[];
    uint32_t rawa = smem_u32(dynraw);
    char* smb = dynraw + (((rawa + 1023) & ~1023u) - rawa);
    const uint32_t sb = smem_u32(smb);

    const int v  = blockIdx.z;
    const int m0 = blockIdx.x * 128;
    const int n0 = blockIdx.y * 128;
    const int t  = threadIdx.x;
    const int lane = t & 31;
    const int w = t >> 5;
    const int mw = (w >> 2) * 64;
    const int nw = (w & 3) * 32;

    float acc[4][4][4];
#pragma unroll
    for (int i = 0; i < 4; i++)
#pragma unroll
        for (int j = 0; j < 4; j++)
#pragma unroll
            for (int q = 0; q < 4; q++) acc[i][j][q] = 0.f;

    const __half* Wh = g_Whi + ((size_t)v * NO + n0) * NI;
    const __half* Wl = g_Wlo + ((size_t)v * NO + n0) * NI;

    float4 areg[8];
    load_A_regs(areg, feat, m0, v, 0, t);

#pragma unroll
    for (int c = 0; c < 4; c++) {
        if (c) __syncthreads();            // prev chunk consumers done
        issue_B(sb, Wh, Wl, c * 64, t);    // cp.async into the single stage
        CP_COMMIT();
        store_A_smem(smb, areg, t);        // cvt+STS overlaps cp.async
        if (c < 3) load_A_regs(areg, feat, m0, v, (c + 1) * 64, t);  // prefetch
        CP_WAIT(0);
        __syncthreads();

#pragma unroll
        for (int ks = 0; ks < 4; ks++) {
            uint32_t bh[4][2], bl[4][2];
            {
                int brow = nw + (lane & 7);
                int bk = ks * 16 + ((lane >> 3) & 1) * 8;
#pragma unroll
                for (int nt = 0; nt < 4; nt++) {
                    uint32_t addr = sb + B_HI + SWZ((brow + nt * 8) * 128 + bk * 2);
                    ldsm_x2(bh[nt], addr);
                    ldsm_x2(bl[nt], addr + (B_LO - B_HI));
                }
            }
            int arow = mw + (lane & 7) + ((lane >> 3) & 1) * 8;
            int ak = ks * 16 + ((lane >> 4) & 1) * 8;
#pragma unroll
            for (int mt = 0; mt < 4; mt++) {
                uint32_t ra[4];
                ldsm_x4(ra, sb + A_OFF + SWZ((arow + mt * 16) * 128 + ak * 2));
#pragma unroll
                for (int nt = 0; nt < 4; nt++) {
                    mma_f16(acc[mt][nt], ra, bh[nt]);
                    mma_f16(acc[mt][nt], ra, bl[nt]);
                }
            }
        }
    }

    // ---- epilogue: bias + store h (fp16) + shuffle-reduced column stats
#pragma unroll
    for (int nt = 0; nt < 4; nt++) {
        const int nl = nw + nt * 8 + (lane & 3) * 2;   // col in block tile (even)
        const int n = n0 + nl;
        float2 bv = *(const float2*)(bias + v * NO + n);
        float2 sum2 = make_float2(0.f, 0.f), sq2 = make_float2(0.f, 0.f);
#pragma unroll
        for (int mt = 0; mt < 4; mt++) {
            int mlo = m0 + mw + mt * 16 + (lane >> 2);
            float2 o0, o1;
            o0.x = acc[mt][nt][0] + bv.x;
            o0.y = acc[mt][nt][1] + bv.y;
            o1.x = acc[mt][nt][2] + bv.x;
            o1.y = acc[mt][nt][3] + bv.y;
            __half2 p0 = __floats2half2_rn(o0.x, o0.y);
            __half2 p1 = __floats2half2_rn(o1.x, o1.y);
            *(uint32_t*)(g_h16 + (size_t)mlo * (NV * NO) + v * NO + n) =
                *(uint32_t*)&p0;
            *(uint32_t*)(g_h16 + (size_t)(mlo + 8) * (NV * NO) + v * NO + n) =
                *(uint32_t*)&p1;
            sum2.x += o0.x + o1.x;
            sum2.y += o0.y + o1.y;
            sq2.x += fmaf(o0.x, o0.x, o1.x * o1.x);
            sq2.y += fmaf(o0.y, o0.y, o1.y * o1.y);
        }
#pragma unroll
        for (int msk = 4; msk <= 16; msk <<= 1) {
            sum2.x += __shfl_xor_sync(0xffffffffu, sum2.x, msk);
            sum2.y += __shfl_xor_sync(0xffffffffu, sum2.y, msk);
            sq2.x  += __shfl_xor_sync(0xffffffffu, sq2.x, msk);
            sq2.y  += __shfl_xor_sync(0xffffffffu, sq2.y, msk);
        }
        if (lane < 4) {
            atomicAdd(&g_sum[v * NO + n],     sum2.x);
            atomicAdd(&g_sum[v * NO + n + 1], sum2.y);
            atomicAdd(&g_sqs[v * NO + n],     sq2.x);
            atomicAdd(&g_sqs[v * NO + n + 1], sq2.y);
        }
    }
}

// ---------------------------------------------------------------------------
// Kernel C: finalize BN fold
// ---------------------------------------------------------------------------
__global__ __launch_bounds__(256) void stats_fin(const float* __restrict__ gamma,
                                                 const float* __restrict__ beta) {
    const int col = blockIdx.x * 256 + threadIdx.x;
    float mean = g_sum[col] * (1.f / NB);
    float var  = g_sqs[col] * (1.f / NB) - mean * mean;
    float s    = gamma[col] * rsqrtf(var + EPS);
    g_s[col] = s;
    g_t[col] = fmaf(-mean, s, beta[col]);
}

// ---------------------------------------------------------------------------
// Kernel D: tensorized mix, fp16 2-term: adj single, hs = s*h+t split hi/lo.
// out[b,u,o] = relu( sum_v adj[u,v] * hs[v,o] )
// ---------------------------------------------------------------------------
static constexpr int OPAD = 264;                 // hs row stride (fp16 elems)
static constexpr int HS_HI = 0;                  // 64*264*2 = 33792 B
static constexpr int HS_LO = 33792;
static constexpr int ADJ_OFF = 67584;            // 64 rows x 72 elems x 2B
static constexpr int MIX_DSMEM = 76800 + 1024;

__global__ __launch_bounds__(256, 2) void mix_tc(float* __restrict__ out) {
    extern __shared__ char dynraw[];
    uint32_t rawa = smem_u32(dynraw);
    char* smb = dynraw + (((rawa + 1023) & ~1023u) - rawa);
    const uint32_t sbase = smem_u32(smb);

    const int b = blockIdx.x;
    const int t = threadIdx.x;
    const int lane = t & 31;
    const int w = t >> 5;

    // ---- stage hs = s*h + t (from fp16 h), split fp16 hi/lo, [v][OPAD]
    const uint2*  h2 = (const uint2*)(g_h16 + (size_t)b * NV * NO);  // 4 halves
    const float4* s4 = (const float4*)g_s;
    const float4* t4 = (const float4*)g_t;
#pragma unroll
    for (int r = 0; r < 16; r++) {
        int idx = t + r * 256;            // 0..4095 (4 elems each)
        int v = idx >> 6, oq = idx & 63;
        uint2 hp = h2[idx];
        __half2 ha = *(__half2*)&hp.x, hb = *(__half2*)&hp.y;
        float4 sv = s4[idx], tv = t4[idx];
        float x0 = fmaf(__half2float(ha.x), sv.x, tv.x);
        float x1 = fmaf(__half2float(ha.y), sv.y, tv.y);
        float x2 = fmaf(__half2float(hb.x), sv.z, tv.z);
        float x3 = fmaf(__half2float(hb.y), sv.w, tv.w);
        __half h0 = __float2half_rn(x0);
        __half h1 = __float2half_rn(x1);
        __half h2c = __float2half_rn(x2);
        __half h3 = __float2half_rn(x3);
        __half l0 = __float2half_rn(x0 - __half2float(h0));
        __half l1 = __float2half_rn(x1 - __half2float(h1));
        __half l2 = __float2half_rn(x2 - __half2float(h2c));
        __half l3 = __float2half_rn(x3 - __half2float(h3));
        __half2 hp0 = {h0, h1}, hp1 = {h2c, h3};
        __half2 lp0 = {l0, l1}, lp1 = {l2, l3};
        uint32_t off = (uint32_t)(v * (OPAD * 2) + oq * 8);
        *(uint2*)(smb + HS_HI + off) =
            make_uint2(*(uint32_t*)&hp0, *(uint32_t*)&hp1);
        *(uint2*)(smb + HS_LO + off) =
            make_uint2(*(uint32_t*)&lp0, *(uint32_t*)&lp1);
    }
    // ---- stage adj (single fp16), [u][72] rows
#pragma unroll
    for (int r = 0; r < 8; r++) {
        int idx = t + r * 256;            // 0..2047 uint32s (2 fp16 each)
        int u = idx >> 5, q = idx & 31;
        *(uint32_t*)(smb + ADJ_OFF + u * 144 + q * 4) =
            ((const uint32_t*)g_adj16)[idx];
    }
    __syncthreads();

    const int mw = (w >> 1) * 16;     // u tile (4 tiles of 16)
    const int nw = (w & 1) * 128;     // o half

    float acc[16][4];
#pragma unroll
    for (int i = 0; i < 16; i++)
#pragma unroll
        for (int q = 0; q < 4; q++) acc[i][q] = 0.f;

#pragma unroll
    for (int ks = 0; ks < 4; ks++) {
        uint32_t ah[4];
        uint32_t aaddr = sbase + ADJ_OFF + (mw + (lane & 15)) * 144 +
                         (ks * 16 + (lane >> 4) * 8) * 2;
        ldsm_x4(ah, aaddr);

        uint32_t brow = sbase + HS_HI + (ks * 16 + (lane & 15)) * (OPAD * 2);
#pragma unroll
        for (int nt = 0; nt < 16; nt++) {
            int n0 = nw + nt * 8;
            uint32_t bh[2], bl[2];
            ldsm_x2t(bh, brow + n0 * 2);
            ldsm_x2t(bl, brow + n0 * 2 + (HS_LO - HS_HI));
            mma_f16(acc[nt], ah, bh);
            mma_f16(acc[nt], ah, bl);
        }
    }

    // ---- epilogue: relu + store
    float* ob = out + (size_t)b * NV * NO;
    const int u0 = mw + (lane >> 2);
#pragma unroll
    for (int nt = 0; nt < 16; nt++) {
        int o = nw + nt * 8 + (lane & 3) * 2;
        float2 r0, r1;
        r0.x = fmaxf(acc[nt][0], 0.f);
        r0.y = fmaxf(acc[nt][1], 0.f);
        r1.x = fmaxf(acc[nt][2], 0.f);
        r1.y = fmaxf(acc[nt][3], 0.f);
        *(float2*)(ob + (size_t)u0 * NO + o) = r0;
        *(float2*)(ob + (size_t)(u0 + 8) * NO + o) = r1;
    }
}

// ---------------------------------------------------------------------------
extern "C" void kernel_launch(void* const* d_in, const int* in_sizes, int n_in,
                              void* d_out, int out_size) {
    const float* feat  = (const float*)d_in[0];
    const float* adj   = (const float*)d_in[1];
    const float* W     = (const float*)d_in[2];
    const float* bias  = (const float*)d_in[3];
    const float* gamma = (const float*)d_in[4];
    const float* beta  = (const float*)d_in[5];
    float* out = (float*)d_out;

    cudaFuncSetAttribute(gemm_mma, cudaFuncAttributeMaxDynamicSharedMemorySize,
                         GEMM_DSMEM);
    cudaFuncSetAttribute(mix_tc, cudaFuncAttributeMaxDynamicSharedMemorySize,
                         MIX_DSMEM);

    convert_W<<<dim3(NO / 64, NV), 256>>>(W);
    convert_adj<<<16, 256>>>(adj);   // also zeroes g_sum/g_sqs
    gemm_mma<<<dim3(NB / 128, NO / 128, NV), 256, GEMM_DSMEM>>>(feat, bias);
    stats_fin<<<64, 256>>>(gamma, beta);
    mix_tc<<<NB, 256, MIX_DSMEM>>>(out);
}

// round 13
// speedup vs baseline: 1.2846x; 1.0077x over previous
#include <cuda_runtime.h>
#include <cuda_bf16.h>
#include <cuda_fp16.h>
#include <cstdint>

#define NB 1024
#define NV 64
#define NI 256
#define NO 256
constexpr float EPS = 1e-5f;

// ---------------------------------------------------------------------------
// Device scratch
// ---------------------------------------------------------------------------
__device__ __half g_h16[(size_t)NB * NV * NO];         // 32 MB: h (fp16)
__device__ __half g_Whi[(size_t)NV * NO * NI];         // 8 MB, layout [v][o][i]
__device__ __half g_Wlo[(size_t)NV * NO * NI];         // 8 MB
__device__ __half g_adj16[NV * NV];
__device__ float g_sum[NV * NO];
__device__ float g_sqs[NV * NO];
__device__ float g_s[NV * NO];
__device__ float g_t[NV * NO];

// ---------------------------------------------------------------------------
// Helpers (baseline PTX only)
// ---------------------------------------------------------------------------
__device__ __forceinline__ uint32_t smem_u32(const void* p) {
    uint32_t a;
    asm("{ .reg .u64 t; cvta.to.shared.u64 t, %1; cvt.u32.u64 %0, t; }"
        : "=r"(a) : "l"(p));
    return a;
}
#define SWZ(off) ((uint32_t)(off) ^ ((((uint32_t)(off)) >> 3) & 0x70))  // 128B rows

__device__ __forceinline__ void ldsm_x4(uint32_t* r, uint32_t addr) {
    asm volatile("ldmatrix.sync.aligned.m8n8.x4.shared.b16 {%0,%1,%2,%3}, [%4];"
                 : "=r"(r[0]), "=r"(r[1]), "=r"(r[2]), "=r"(r[3]) : "r"(addr));
}
__device__ __forceinline__ void ldsm_x2(uint32_t* r, uint32_t addr) {
    asm volatile("ldmatrix.sync.aligned.m8n8.x2.shared.b16 {%0,%1}, [%2];"
                 : "=r"(r[0]), "=r"(r[1]) : "r"(addr));
}
__device__ __forceinline__ void ldsm_x2t(uint32_t* r, uint32_t addr) {
    asm volatile("ldmatrix.sync.aligned.m8n8.x2.trans.shared.b16 {%0,%1}, [%2];"
                 : "=r"(r[0]), "=r"(r[1]) : "r"(addr));
}
__device__ __forceinline__ void mma_f16(float* d, const uint32_t* a,
                                        const uint32_t* b) {
    asm volatile(
        "mma.sync.aligned.m16n8k16.row.col.f32.f16.f16.f32 "
        "{%0,%1,%2,%3}, {%4,%5,%6,%7}, {%8,%9}, {%0,%1,%2,%3};"
        : "+f"(d[0]), "+f"(d[1]), "+f"(d[2]), "+f"(d[3])
        : "r"(a[0]), "r"(a[1]), "r"(a[2]), "r"(a[3]), "r"(b[0]), "r"(b[1]));
}
__device__ __forceinline__ void cp16(uint32_t smem, const void* g) {
    asm volatile("cp.async.cg.shared.global [%0], [%1], 16;"
                 :: "r"(smem), "l"(g) : "memory");
}
#define CP_COMMIT() asm volatile("cp.async.commit_group;" ::: "memory")
#define CP_WAIT(N)  asm volatile("cp.async.wait_group %0;" :: "n"(N) : "memory")

// ---------------------------------------------------------------------------
// Kernel A: split W into fp16 hi/lo, transposed to K-major [v][o][i]
// ---------------------------------------------------------------------------
__global__ __launch_bounds__(256) void convert_W(const float* __restrict__ W) {
    __shared__ float tile[256][65];
    const int v = blockIdx.y, o0 = blockIdx.x * 64;
    const int t = threadIdx.x;
    const float* src = W + (size_t)v * NI * NO + o0;
#pragma unroll 8
    for (int r = 0; r < 64; r++) {
        int idx = r * 256 + t;
        int i = idx >> 6, o = idx & 63;
        tile[i][o] = src[(size_t)i * NO + o];
    }
    __syncthreads();
    __half* dh = g_Whi + ((size_t)v * NO + o0) * NI;
    __half* dl = g_Wlo + ((size_t)v * NO + o0) * NI;
#pragma unroll 8
    for (int r = 0; r < 64; r++) {
        float x = tile[t][r];
        __half hi = __float2half_rn(x);
        __half lo = __float2half_rn(x - __half2float(hi));
        dh[(size_t)r * NI + t] = hi;
        dl[(size_t)r * NI + t] = lo;
    }
}

// ---------------------------------------------------------------------------
// Kernel A2: adj -> fp16 AND zero stats accumulators. grid 16 x 256.
// ---------------------------------------------------------------------------
__global__ void convert_adj(const float* __restrict__ adj) {
    int i = blockIdx.x * 256 + threadIdx.x;   // 0..4095
    g_adj16[i] = __float2half_rn(adj[i]);
    ((float4*)g_sum)[i] = make_float4(0.f, 0.f, 0.f, 0.f);
    ((float4*)g_sqs)[i] = make_float4(0.f, 0.f, 0.f, 0.f);
}

// ---------------------------------------------------------------------------
// Kernel B: R7-structure GEMM, fp16 single-A + split-W: 2 MMAs per k-step.
// grid (NB/128, NO/128, NV), block 256 (8 warps), tile 128x128, K-chunk 64.
// h stored as fp16. smem: A 16KB + Bhi 16KB + Blo 16KB = 48KB -> occ 2.
// ---------------------------------------------------------------------------
static constexpr int A_OFF = 0;
static constexpr int B_HI = 16384;
static constexpr int B_LO = 32768;
static constexpr int GEMM_DSMEM = 49152 + 1024;

__device__ __forceinline__ void load_A_regs(float4* areg,
                                            const float* __restrict__ feat,
                                            int m0, int v, int k0, int t) {
#pragma unroll
    for (int r = 0; r < 8; r++) {
        int idx = t + r * 256;            // 0..2047 float4s (128m x 64k)
        int m = idx >> 4, kq = idx & 15;
        areg[r] = *(const float4*)(feat +
                   ((size_t)(m0 + m) * NV + v) * NI + k0 + kq * 4);
    }
}
__device__ __forceinline__ void store_A_smem(char* buf, const float4* areg,
                                             int t) {
#pragma unroll
    for (int r = 0; r < 8; r++) {
        int idx = t + r * 256;
        int m = idx >> 4, kq = idx & 15;
        float4 x = areg[r];
        __half2 p0 = __floats2half2_rn(x.x, x.y);
        __half2 p1 = __floats2half2_rn(x.z, x.w);
        uint32_t off = SWZ(m * 128 + kq * 8);
        *(uint2*)(buf + A_OFF + off) =
            make_uint2(*(uint32_t*)&p0, *(uint32_t*)&p1);
    }
}
__device__ __forceinline__ void issue_B(uint32_t sb,
                                        const __half* __restrict__ Wh,
                                        const __half* __restrict__ Wl,
                                        int k0, int t) {
#pragma unroll
    for (int r = 0; r < 4; r++) {
        int idx = t + r * 256;            // 0..1023 16B chunks (128n x 64k)
        int n = idx >> 3, kc = idx & 7;
        uint32_t off = SWZ(n * 128 + kc * 16);
        cp16(sb + B_HI + off, Wh + (size_t)n * NI + k0 + kc * 8);
        cp16(sb + B_LO + off, Wl + (size_t)n * NI + k0 + kc * 8);
    }
}

__global__ __launch_bounds__(256, 2) void gemm_mma(const float* __restrict__ feat,
                                                   const float* __restrict__ bias) {
    extern __shared__ char dynraw[];
    uint32_t rawa = smem_u32(dynraw);
    char* smb = dynraw + (((rawa + 1023) & ~1023u) - rawa);
    const uint32_t sb = smem_u32(smb);

    const int v  = blockIdx.z;
    const int m0 = blockIdx.x * 128;
    const int n0 = blockIdx.y * 128;
    const int t  = threadIdx.x;
    const int lane = t & 31;
    const int w = t >> 5;
    const int mw = (w >> 2) * 64;
    const int nw = (w & 3) * 32;

    float acc[4][4][4];
#pragma unroll
    for (int i = 0; i < 4; i++)
#pragma unroll
        for (int j = 0; j < 4; j++)
#pragma unroll
            for (int q = 0; q < 4; q++) acc[i][j][q] = 0.f;

    const __half* Wh = g_Whi + ((size_t)v * NO + n0) * NI;
    const __half* Wl = g_Wlo + ((size_t)v * NO + n0) * NI;

    float4 areg[8];
    load_A_regs(areg, feat, m0, v, 0, t);

#pragma unroll
    for (int c = 0; c < 4; c++) {
        if (c) __syncthreads();            // prev chunk consumers done
        issue_B(sb, Wh, Wl, c * 64, t);    // cp.async into the single stage
        CP_COMMIT();
        store_A_smem(smb, areg, t);        // cvt+STS overlaps cp.async
        if (c < 3) load_A_regs(areg, feat, m0, v, (c + 1) * 64, t);  // prefetch
        CP_WAIT(0);
        __syncthreads();

#pragma unroll
        for (int ks = 0; ks < 4; ks++) {
            uint32_t bh[4][2], bl[4][2];
            {
                int brow = nw + (lane & 7);
                int bk = ks * 16 + ((lane >> 3) & 1) * 8;
#pragma unroll
                for (int nt = 0; nt < 4; nt++) {
                    uint32_t addr = sb + B_HI + SWZ((brow + nt * 8) * 128 + bk * 2);
                    ldsm_x2(bh[nt], addr);
                    ldsm_x2(bl[nt], addr + (B_LO - B_HI));
                }
            }
            int arow = mw + (lane & 7) + ((lane >> 3) & 1) * 8;
            int ak = ks * 16 + ((lane >> 4) & 1) * 8;
#pragma unroll
            for (int mt = 0; mt < 4; mt++) {
                uint32_t ra[4];
                ldsm_x4(ra, sb + A_OFF + SWZ((arow + mt * 16) * 128 + ak * 2));
#pragma unroll
                for (int nt = 0; nt < 4; nt++) {
                    mma_f16(acc[mt][nt], ra, bh[nt]);
                    mma_f16(acc[mt][nt], ra, bl[nt]);
                }
            }
        }
    }

    // ---- epilogue: bias + store h (fp16) + shuffle-reduced column stats
#pragma unroll
    for (int nt = 0; nt < 4; nt++) {
        const int nl = nw + nt * 8 + (lane & 3) * 2;   // col in block tile (even)
        const int n = n0 + nl;
        float2 bv = *(const float2*)(bias + v * NO + n);
        float2 sum2 = make_float2(0.f, 0.f), sq2 = make_float2(0.f, 0.f);
#pragma unroll
        for (int mt = 0; mt < 4; mt++) {
            int mlo = m0 + mw + mt * 16 + (lane >> 2);
            float2 o0, o1;
            o0.x = acc[mt][nt][0] + bv.x;
            o0.y = acc[mt][nt][1] + bv.y;
            o1.x = acc[mt][nt][2] + bv.x;
            o1.y = acc[mt][nt][3] + bv.y;
            __half2 p0 = __floats2half2_rn(o0.x, o0.y);
            __half2 p1 = __floats2half2_rn(o1.x, o1.y);
            *(uint32_t*)(g_h16 + (size_t)mlo * (NV * NO) + v * NO + n) =
                *(uint32_t*)&p0;
            *(uint32_t*)(g_h16 + (size_t)(mlo + 8) * (NV * NO) + v * NO + n) =
                *(uint32_t*)&p1;
            sum2.x += o0.x + o1.x;
            sum2.y += o0.y + o1.y;
            sq2.x += fmaf(o0.x, o0.x, o1.x * o1.x);
            sq2.y += fmaf(o0.y, o0.y, o1.y * o1.y);
        }
#pragma unroll
        for (int msk = 4; msk <= 16; msk <<= 1) {
            sum2.x += __shfl_xor_sync(0xffffffffu, sum2.x, msk);
            sum2.y += __shfl_xor_sync(0xffffffffu, sum2.y, msk);
            sq2.x  += __shfl_xor_sync(0xffffffffu, sq2.x, msk);
            sq2.y  += __shfl_xor_sync(0xffffffffu, sq2.y, msk);
        }
        if (lane < 4) {
            atomicAdd(&g_sum[v * NO + n],     sum2.x);
            atomicAdd(&g_sum[v * NO + n + 1], sum2.y);
            atomicAdd(&g_sqs[v * NO + n],     sq2.x);
            atomicAdd(&g_sqs[v * NO + n + 1], sq2.y);
        }
    }
}

// ---------------------------------------------------------------------------
// Kernel C: finalize BN fold
// ---------------------------------------------------------------------------
__global__ __launch_bounds__(256) void stats_fin(const float* __restrict__ gamma,
                                                 const float* __restrict__ beta) {
    const int col = blockIdx.x * 256 + threadIdx.x;
    float mean = g_sum[col] * (1.f / NB);
    float var  = g_sqs[col] * (1.f / NB) - mean * mean;
    float s    = gamma[col] * rsqrtf(var + EPS);
    g_s[col] = s;
    g_t[col] = fmaf(-mean, s, beta[col]);
}

// ---------------------------------------------------------------------------
// Kernel D: tensorized mix, fp16 2-term: adj single, hs = s*h+t split hi/lo.
// out[b,u,o] = relu( sum_v adj[u,v] * hs[v,o] )
// ---------------------------------------------------------------------------
static constexpr int OPAD = 264;                 // hs row stride (fp16 elems)
static constexpr int HS_HI = 0;                  // 64*264*2 = 33792 B
static constexpr int HS_LO = 33792;
static constexpr int ADJ_OFF = 67584;            // 64 rows x 72 elems x 2B
static constexpr int MIX_DSMEM = 76800 + 1024;

__global__ __launch_bounds__(256, 2) void mix_tc(float* __restrict__ out) {
    extern __shared__ char dynraw[];
    uint32_t rawa = smem_u32(dynraw);
    char* smb = dynraw + (((rawa + 1023) & ~1023u) - rawa);
    const uint32_t sbase = smem_u32(smb);

    const int b = blockIdx.x;
    const int t = threadIdx.x;
    const int lane = t & 31;
    const int w = t >> 5;

    // ---- stage hs = s*h + t (from fp16 h), split fp16 hi/lo, [v][OPAD]
    const uint2*  h2 = (const uint2*)(g_h16 + (size_t)b * NV * NO);  // 4 halves
    const float4* s4 = (const float4*)g_s;
    const float4* t4 = (const float4*)g_t;
#pragma unroll
    for (int r = 0; r < 16; r++) {
        int idx = t + r * 256;            // 0..4095 (4 elems each)
        int v = idx >> 6, oq = idx & 63;
        uint2 hp = h2[idx];
        __half2 ha = *(__half2*)&hp.x, hb = *(__half2*)&hp.y;
        float4 sv = s4[idx], tv = t4[idx];
        float x0 = fmaf(__half2float(ha.x), sv.x, tv.x);
        float x1 = fmaf(__half2float(ha.y), sv.y, tv.y);
        float x2 = fmaf(__half2float(hb.x), sv.z, tv.z);
        float x3 = fmaf(__half2float(hb.y), sv.w, tv.w);
        __half h0 = __float2half_rn(x0);
        __half h1 = __float2half_rn(x1);
        __half h2c = __float2half_rn(x2);
        __half h3 = __float2half_rn(x3);
        __half l0 = __float2half_rn(x0 - __half2float(h0));
        __half l1 = __float2half_rn(x1 - __half2float(h1));
        __half l2 = __float2half_rn(x2 - __half2float(h2c));
        __half l3 = __float2half_rn(x3 - __half2float(h3));
        __half2 hp0 = {h0, h1}, hp1 = {h2c, h3};
        __half2 lp0 = {l0, l1}, lp1 = {l2, l3};
        uint32_t off = (uint32_t)(v * (OPAD * 2) + oq * 8);
        *(uint2*)(smb + HS_HI + off) =
            make_uint2(*(uint32_t*)&hp0, *(uint32_t*)&hp1);
        *(uint2*)(smb + HS_LO + off) =
            make_uint2(*(uint32_t*)&lp0, *(uint32_t*)&lp1);
    }
    // ---- stage adj (single fp16), [u][72] rows
#pragma unroll
    for (int r = 0; r < 8; r++) {
        int idx = t + r * 256;            // 0..2047 uint32s (2 fp16 each)
        int u = idx >> 5, q = idx & 31;
        *(uint32_t*)(smb + ADJ_OFF + u * 144 + q * 4) =
            ((const uint32_t*)g_adj16)[idx];
    }
    __syncthreads();

    const int mw = (w >> 1) * 16;     // u tile (4 tiles of 16)
    const int nw = (w & 1) * 128;     // o half

    float acc[16][4];
#pragma unroll
    for (int i = 0; i < 16; i++)
#pragma unroll
        for (int q = 0; q < 4; q++) acc[i][q] = 0.f;

#pragma unroll
    for (int ks = 0; ks < 4; ks++) {
        uint32_t ah[4];
        uint32_t aaddr = sbase + ADJ_OFF + (mw + (lane & 15)) * 144 +
                         (ks * 16 + (lane >> 4) * 8) * 2;
        ldsm_x4(ah, aaddr);

        uint32_t brow = sbase + HS_HI + (ks * 16 + (lane & 15)) * (OPAD * 2);
#pragma unroll
        for (int nt = 0; nt < 16; nt++) {
            int n0 = nw + nt * 8;
            uint32_t bh[2], bl[2];
            ldsm_x2t(bh, brow + n0 * 2);
            ldsm_x2t(bl, brow + n0 * 2 + (HS_LO - HS_HI));
            mma_f16(acc[nt], ah, bh);
            mma_f16(acc[nt], ah, bl);
        }
    }

    // ---- epilogue: relu + store
    float* ob = out + (size_t)b * NV * NO;
    const int u0 = mw + (lane >> 2);
#pragma unroll
    for (int nt = 0; nt < 16; nt++) {
        int o = nw + nt * 8 + (lane & 3) * 2;
        float2 r0, r1;
        r0.x = fmaxf(acc[nt][0], 0.f);
        r0.y = fmaxf(acc[nt][1], 0.f);
        r1.x = fmaxf(acc[nt][2], 0.f);
        r1.y = fmaxf(acc[nt][3], 0.f);
        *(float2*)(ob + (size_t)u0 * NO + o) = r0;
        *(float2*)(ob + (size_t)(u0 + 8) * NO + o) = r1;
    }
}

// ---------------------------------------------------------------------------
extern "C" void kernel_launch(void* const* d_in, const int* in_sizes, int n_in,
                              void* d_out, int out_size) {
    const float* feat  = (const float*)d_in[0];
    const float* adj   = (const float*)d_in[1];
    const float* W     = (const float*)d_in[2];
    const float* bias  = (const float*)d_in[3];
    const float* gamma = (const float*)d_in[4];
    const float* beta  = (const float*)d_in[5];
    float* out = (float*)d_out;

    cudaFuncSetAttribute(gemm_mma, cudaFuncAttributeMaxDynamicSharedMemorySize,
                         GEMM_DSMEM);
    cudaFuncSetAttribute(mix_tc, cudaFuncAttributeMaxDynamicSharedMemorySize,
                         MIX_DSMEM);

    convert_W<<<dim3(NO / 64, NV), 256>>>(W);
    convert_adj<<<16, 256>>>(adj);   // also zeroes g_sum/g_sqs
    gemm_mma<<<dim3(NB / 128, NO / 128, NV), 256, GEMM_DSMEM>>>(feat, bias);
    stats_fin<<<64, 256>>>(gamma, beta);
    mix_tc<<<NB, 256, MIX_DSMEM>>>(out);
}

// round 14
// speedup vs baseline: 1.4687x; 1.1433x over previous
#include <cuda_runtime.h>
#include <cuda_bf16.h>
#include <cuda_fp16.h>
#include <cstdint>

#define NB 1024
#define NV 64
#define NI 256
#define NO 256
constexpr float EPS = 1e-5f;

// ---------------------------------------------------------------------------
// Device scratch
// ---------------------------------------------------------------------------
__device__ __half g_h16[(size_t)NB * NV * NO];         // 32 MB: h (fp16)
__device__ __half g_W16[(size_t)NV * NO * NI];         // 8 MB, layout [v][o][i]
__device__ __half g_adj16[NV * NV];
__device__ float g_sum[NV * NO];
__device__ float g_sqs[NV * NO];
__device__ float g_s[NV * NO];
__device__ float g_t[NV * NO];

// ---------------------------------------------------------------------------
// Helpers (baseline PTX only)
// ---------------------------------------------------------------------------
__device__ __forceinline__ uint32_t smem_u32(const void* p) {
    uint32_t a;
    asm("{ .reg .u64 t; cvta.to.shared.u64 t, %1; cvt.u32.u64 %0, t; }"
        : "=r"(a) : "l"(p));
    return a;
}
#define SWZ(off) ((uint32_t)(off) ^ ((((uint32_t)(off)) >> 3) & 0x70))  // 128B rows

__device__ __forceinline__ void ldsm_x4(uint32_t* r, uint32_t addr) {
    asm volatile("ldmatrix.sync.aligned.m8n8.x4.shared.b16 {%0,%1,%2,%3}, [%4];"
                 : "=r"(r[0]), "=r"(r[1]), "=r"(r[2]), "=r"(r[3]) : "r"(addr));
}
__device__ __forceinline__ void ldsm_x2(uint32_t* r, uint32_t addr) {
    asm volatile("ldmatrix.sync.aligned.m8n8.x2.shared.b16 {%0,%1}, [%2];"
                 : "=r"(r[0]), "=r"(r[1]) : "r"(addr));
}
__device__ __forceinline__ void ldsm_x2t(uint32_t* r, uint32_t addr) {
    asm volatile("ldmatrix.sync.aligned.m8n8.x2.trans.shared.b16 {%0,%1}, [%2];"
                 : "=r"(r[0]), "=r"(r[1]) : "r"(addr));
}
__device__ __forceinline__ void mma_f16(float* d, const uint32_t* a,
                                        const uint32_t* b) {
    asm volatile(
        "mma.sync.aligned.m16n8k16.row.col.f32.f16.f16.f32 "
        "{%0,%1,%2,%3}, {%4,%5,%6,%7}, {%8,%9}, {%0,%1,%2,%3};"
        : "+f"(d[0]), "+f"(d[1]), "+f"(d[2]), "+f"(d[3])
        : "r"(a[0]), "r"(a[1]), "r"(a[2]), "r"(a[3]), "r"(b[0]), "r"(b[1]));
}
__device__ __forceinline__ void cp16(uint32_t smem, const void* g) {
    asm volatile("cp.async.cg.shared.global [%0], [%1], 16;"
                 :: "r"(smem), "l"(g) : "memory");
}
#define CP_COMMIT() asm volatile("cp.async.commit_group;" ::: "memory")
#define CP_WAIT(N)  asm volatile("cp.async.wait_group %0;" :: "n"(N) : "memory")

// ---------------------------------------------------------------------------
// Kernel A: W -> fp16, transposed to K-major [v][o][i]
// ---------------------------------------------------------------------------
__global__ __launch_bounds__(256) void convert_W(const float* __restrict__ W) {
    __shared__ float tile[256][65];
    const int v = blockIdx.y, o0 = blockIdx.x * 64;
    const int t = threadIdx.x;
    const float* src = W + (size_t)v * NI * NO + o0;
#pragma unroll 8
    for (int r = 0; r < 64; r++) {
        int idx = r * 256 + t;
        int i = idx >> 6, o = idx & 63;
        tile[i][o] = src[(size_t)i * NO + o];
    }
    __syncthreads();
    __half* dh = g_W16 + ((size_t)v * NO + o0) * NI;
#pragma unroll 8
    for (int r = 0; r < 64; r++) {
        dh[(size_t)r * NI + t] = __float2half_rn(tile[t][r]);
    }
}

// ---------------------------------------------------------------------------
// Kernel A2: adj -> fp16 AND zero stats accumulators. grid 16 x 256.
// ---------------------------------------------------------------------------
__global__ void convert_adj(const float* __restrict__ adj) {
    int i = blockIdx.x * 256 + threadIdx.x;   // 0..4095
    g_adj16[i] = __float2half_rn(adj[i]);
    ((float4*)g_sum)[i] = make_float4(0.f, 0.f, 0.f, 0.f);
    ((float4*)g_sqs)[i] = make_float4(0.f, 0.f, 0.f, 0.f);
}

// ---------------------------------------------------------------------------
// Kernel B: R7-structure GEMM, pure fp16 (1 MMA per k-step).
// grid (NB/128, NO/128, NV), block 256 (8 warps), tile 128x128, K-chunk 64.
// h stored as fp16. smem: A 16KB + B 16KB = 32KB -> occ 2.
// ---------------------------------------------------------------------------
static constexpr int A_OFF = 0;
static constexpr int B_OFF = 16384;
static constexpr int GEMM_DSMEM = 32768 + 1024;

__device__ __forceinline__ void load_A_regs(float4* areg,
                                            const float* __restrict__ feat,
                                            int m0, int v, int k0, int t) {
#pragma unroll
    for (int r = 0; r < 8; r++) {
        int idx = t + r * 256;            // 0..2047 float4s (128m x 64k)
        int m = idx >> 4, kq = idx & 15;
        areg[r] = *(const float4*)(feat +
                   ((size_t)(m0 + m) * NV + v) * NI + k0 + kq * 4);
    }
}
__device__ __forceinline__ void store_A_smem(char* buf, const float4* areg,
                                             int t) {
#pragma unroll
    for (int r = 0; r < 8; r++) {
        int idx = t + r * 256;
        int m = idx >> 4, kq = idx & 15;
        float4 x = areg[r];
        __half2 p0 = __floats2half2_rn(x.x, x.y);
        __half2 p1 = __floats2half2_rn(x.z, x.w);
        uint32_t off = SWZ(m * 128 + kq * 8);
        *(uint2*)(buf + A_OFF + off) =
            make_uint2(*(uint32_t*)&p0, *(uint32_t*)&p1);
    }
}
__device__ __forceinline__ void issue_B(uint32_t sb,
                                        const __half* __restrict__ Wp,
                                        int k0, int t) {
#pragma unroll
    for (int r = 0; r < 4; r++) {
        int idx = t + r * 256;            // 0..1023 16B chunks (128n x 64k)
        int n = idx >> 3, kc = idx & 7;
        uint32_t off = SWZ(n * 128 + kc * 16);
        cp16(sb + B_OFF + off, Wp + (size_t)n * NI + k0 + kc * 8);
    }
}

__global__ __launch_bounds__(256, 2) void gemm_mma(const float* __restrict__ feat,
                                                   const float* __restrict__ bias) {
    extern __shared__ char dynraw[];
    uint32_t rawa = smem_u32(dynraw);
    char* smb = dynraw + (((rawa + 1023) & ~1023u) - rawa);
    const uint32_t sb = smem_u32(smb);

    const int v  = blockIdx.z;
    const int m0 = blockIdx.x * 128;
    const int n0 = blockIdx.y * 128;
    const int t  = threadIdx.x;
    const int lane = t & 31;
    const int w = t >> 5;
    const int mw = (w >> 2) * 64;
    const int nw = (w & 3) * 32;

    float acc[4][4][4];
#pragma unroll
    for (int i = 0; i < 4; i++)
#pragma unroll
        for (int j = 0; j < 4; j++)
#pragma unroll
            for (int q = 0; q < 4; q++) acc[i][j][q] = 0.f;

    const __half* Wp = g_W16 + ((size_t)v * NO + n0) * NI;

    float4 areg[8];
    load_A_regs(areg, feat, m0, v, 0, t);

#pragma unroll
    for (int c = 0; c < 4; c++) {
        if (c) __syncthreads();            // prev chunk consumers done
        issue_B(sb, Wp, c * 64, t);        // cp.async into the single stage
        CP_COMMIT();
        store_A_smem(smb, areg, t);        // cvt+STS overlaps cp.async
        if (c < 3) load_A_regs(areg, feat, m0, v, (c + 1) * 64, t);  // prefetch
        CP_WAIT(0);
        __syncthreads();

#pragma unroll
        for (int ks = 0; ks < 4; ks++) {
            uint32_t bh[4][2];
            {
                int brow = nw + (lane & 7);
                int bk = ks * 16 + ((lane >> 3) & 1) * 8;
#pragma unroll
                for (int nt = 0; nt < 4; nt++) {
                    ldsm_x2(bh[nt],
                            sb + B_OFF + SWZ((brow + nt * 8) * 128 + bk * 2));
                }
            }
            int arow = mw + (lane & 7) + ((lane >> 3) & 1) * 8;
            int ak = ks * 16 + ((lane >> 4) & 1) * 8;
#pragma unroll
            for (int mt = 0; mt < 4; mt++) {
                uint32_t ra[4];
                ldsm_x4(ra, sb + A_OFF + SWZ((arow + mt * 16) * 128 + ak * 2));
#pragma unroll
                for (int nt = 0; nt < 4; nt++) {
                    mma_f16(acc[mt][nt], ra, bh[nt]);
                }
            }
        }
    }

    // ---- epilogue: bias + store h (fp16) + shuffle-reduced column stats
#pragma unroll
    for (int nt = 0; nt < 4; nt++) {
        const int nl = nw + nt * 8 + (lane & 3) * 2;   // col in block tile (even)
        const int n = n0 + nl;
        float2 bv = *(const float2*)(bias + v * NO + n);
        float2 sum2 = make_float2(0.f, 0.f), sq2 = make_float2(0.f, 0.f);
#pragma unroll
        for (int mt = 0; mt < 4; mt++) {
            int mlo = m0 + mw + mt * 16 + (lane >> 2);
            float2 o0, o1;
            o0.x = acc[mt][nt][0] + bv.x;
            o0.y = acc[mt][nt][1] + bv.y;
            o1.x = acc[mt][nt][2] + bv.x;
            o1.y = acc[mt][nt][3] + bv.y;
            __half2 p0 = __floats2half2_rn(o0.x, o0.y);
            __half2 p1 = __floats2half2_rn(o1.x, o1.y);
            *(uint32_t*)(g_h16 + (size_t)mlo * (NV * NO) + v * NO + n) =
                *(uint32_t*)&p0;
            *(uint32_t*)(g_h16 + (size_t)(mlo + 8) * (NV * NO) + v * NO + n) =
                *(uint32_t*)&p1;
            sum2.x += o0.x + o1.x;
            sum2.y += o0.y + o1.y;
            sq2.x += fmaf(o0.x, o0.x, o1.x * o1.x);
            sq2.y += fmaf(o0.y, o0.y, o1.y * o1.y);
        }
#pragma unroll
        for (int msk = 4; msk <= 16; msk <<= 1) {
            sum2.x += __shfl_xor_sync(0xffffffffu, sum2.x, msk);
            sum2.y += __shfl_xor_sync(0xffffffffu, sum2.y, msk);
            sq2.x  += __shfl_xor_sync(0xffffffffu, sq2.x, msk);
            sq2.y  += __shfl_xor_sync(0xffffffffu, sq2.y, msk);
        }
        if (lane < 4) {
            atomicAdd(&g_sum[v * NO + n],     sum2.x);
            atomicAdd(&g_sum[v * NO + n + 1], sum2.y);
            atomicAdd(&g_sqs[v * NO + n],     sq2.x);
            atomicAdd(&g_sqs[v * NO + n + 1], sq2.y);
        }
    }
}

// ---------------------------------------------------------------------------
// Kernel C: finalize BN fold
// ---------------------------------------------------------------------------
__global__ __launch_bounds__(256) void stats_fin(const float* __restrict__ gamma,
                                                 const float* __restrict__ beta) {
    const int col = blockIdx.x * 256 + threadIdx.x;
    float mean = g_sum[col] * (1.f / NB);
    float var  = g_sqs[col] * (1.f / NB) - mean * mean;
    float s    = gamma[col] * rsqrtf(var + EPS);
    g_s[col] = s;
    g_t[col] = fmaf(-mean, s, beta[col]);
}

// ---------------------------------------------------------------------------
// Kernel D: tensorized mix, fp16 2-term: adj single, hs = s*h+t split hi/lo.
// out[b,u,o] = relu( sum_v adj[u,v] * hs[v,o] )
// ---------------------------------------------------------------------------
static constexpr int OPAD = 264;                 // hs row stride (fp16 elems)
static constexpr int HS_HI = 0;                  // 64*264*2 = 33792 B
static constexpr int HS_LO = 33792;
static constexpr int ADJ_OFF = 67584;            // 64 rows x 72 elems x 2B
static constexpr int MIX_DSMEM = 76800 + 1024;

__global__ __launch_bounds__(256, 2) void mix_tc(float* __restrict__ out) {
    extern __shared__ char dynraw[];
    uint32_t rawa = smem_u32(dynraw);
    char* smb = dynraw + (((rawa + 1023) & ~1023u) - rawa);
    const uint32_t sbase = smem_u32(smb);

    const int b = blockIdx.x;
    const int t = threadIdx.x;
    const int lane = t & 31;
    const int w = t >> 5;

    // ---- stage hs = s*h + t (from fp16 h), split fp16 hi/lo, [v][OPAD]
    const uint2*  h2 = (const uint2*)(g_h16 + (size_t)b * NV * NO);  // 4 halves
    const float4* s4 = (const float4*)g_s;
    const float4* t4 = (const float4*)g_t;
#pragma unroll
    for (int r = 0; r < 16; r++) {
        int idx = t + r * 256;            // 0..4095 (4 elems each)
        int v = idx >> 6, oq = idx & 63;
        uint2 hp = h2[idx];
        __half2 ha = *(__half2*)&hp.x, hb = *(__half2*)&hp.y;
        float4 sv = s4[idx], tv = t4[idx];
        float x0 = fmaf(__half2float(ha.x), sv.x, tv.x);
        float x1 = fmaf(__half2float(ha.y), sv.y, tv.y);
        float x2 = fmaf(__half2float(hb.x), sv.z, tv.z);
        float x3 = fmaf(__half2float(hb.y), sv.w, tv.w);
        __half h0 = __float2half_rn(x0);
        __half h1 = __float2half_rn(x1);
        __half h2c = __float2half_rn(x2);
        __half h3 = __float2half_rn(x3);
        __half l0 = __float2half_rn(x0 - __half2float(h0));
        __half l1 = __float2half_rn(x1 - __half2float(h1));
        __half l2 = __float2half_rn(x2 - __half2float(h2c));
        __half l3 = __float2half_rn(x3 - __half2float(h3));
        __half2 hp0 = {h0, h1}, hp1 = {h2c, h3};
        __half2 lp0 = {l0, l1}, lp1 = {l2, l3};
        uint32_t off = (uint32_t)(v * (OPAD * 2) + oq * 8);
        *(uint2*)(smb + HS_HI + off) =
            make_uint2(*(uint32_t*)&hp0, *(uint32_t*)&hp1);
        *(uint2*)(smb + HS_LO + off) =
            make_uint2(*(uint32_t*)&lp0, *(uint32_t*)&lp1);
    }
    // ---- stage adj (single fp16), [u][72] rows
#pragma unroll
    for (int r = 0; r < 8; r++) {
        int idx = t + r * 256;            // 0..2047 uint32s (2 fp16 each)
        int u = idx >> 5, q = idx & 31;
        *(uint32_t*)(smb + ADJ_OFF + u * 144 + q * 4) =
            ((const uint32_t*)g_adj16)[idx];
    }
    __syncthreads();

    const int mw = (w >> 1) * 16;     // u tile (4 tiles of 16)
    const int nw = (w & 1) * 128;     // o half

    float acc[16][4];
#pragma unroll
    for (int i = 0; i < 16; i++)
#pragma unroll
        for (int q = 0; q < 4; q++) acc[i][q] = 0.f;

#pragma unroll
    for (int ks = 0; ks < 4; ks++) {
        uint32_t ah[4];
        uint32_t aaddr = sbase + ADJ_OFF + (mw + (lane & 15)) * 144 +
                         (ks * 16 + (lane >> 4) * 8) * 2;
        ldsm_x4(ah, aaddr);

        uint32_t brow = sbase + HS_HI + (ks * 16 + (lane & 15)) * (OPAD * 2);
#pragma unroll
        for (int nt = 0; nt < 16; nt++) {
            int n0 = nw + nt * 8;
            uint32_t bh[2], bl[2];
            ldsm_x2t(bh, brow + n0 * 2);
            ldsm_x2t(bl, brow + n0 * 2 + (HS_LO - HS_HI));
            mma_f16(acc[nt], ah, bh);
            mma_f16(acc[nt], ah, bl);
        }
    }

    // ---- epilogue: relu + store
    float* ob = out + (size_t)b * NV * NO;
    const int u0 = mw + (lane >> 2);
#pragma unroll
    for (int nt = 0; nt < 16; nt++) {
        int o = nw + nt * 8 + (lane & 3) * 2;
        float2 r0, r1;
        r0.x = fmaxf(acc[nt][0], 0.f);
        r0.y = fmaxf(acc[nt][1], 0.f);
        r1.x = fmaxf(acc[nt][2], 0.f);
        r1.y = fmaxf(acc[nt][3], 0.f);
        *(float2*)(ob + (size_t)u0 * NO + o) = r0;
        *(float2*)(ob + (size_t)(u0 + 8) * NO + o) = r1;
    }
}

// ---------------------------------------------------------------------------
extern "C" void kernel_launch(void* const* d_in, const int* in_sizes, int n_in,
                              void* d_out, int out_size) {
    const float* feat  = (const float*)d_in[0];
    const float* adj   = (const float*)d_in[1];
    const float* W     = (const float*)d_in[2];
    const float* bias  = (const float*)d_in[3];
    const float* gamma = (const float*)d_in[4];
    const float* beta  = (const float*)d_in[5];
    float* out = (float*)d_out;

    cudaFuncSetAttribute(gemm_mma, cudaFuncAttributeMaxDynamicSharedMemorySize,
                         GEMM_DSMEM);
    cudaFuncSetAttribute(mix_tc, cudaFuncAttributeMaxDynamicSharedMemorySize,
                         MIX_DSMEM);

    convert_W<<<dim3(NO / 64, NV), 256>>>(W);
    convert_adj<<<16, 256>>>(adj);   // also zeroes g_sum/g_sqs
    gemm_mma<<<dim3(NB / 128, NO / 128, NV), 256, GEMM_DSMEM>>>(feat, bias);
    stats_fin<<<64, 256>>>(gamma, beta);
    mix_tc<<<NB, 256, MIX_DSMEM>>>(out);
}

// round 15
// speedup vs baseline: 1.6276x; 1.1081x over previous
#include <cuda_runtime.h>
#include <cuda_bf16.h>
#include <cuda_fp16.h>
#include <cstdint>

#define NB 1024
#define NV 64
#define NI 256
#define NO 256
constexpr float EPS = 1e-5f;

// ---------------------------------------------------------------------------
// Device scratch
// ---------------------------------------------------------------------------
__device__ __half g_h16[(size_t)NB * NV * NO];   // 32 MB: h (fp16)
__device__ __half g_W16[(size_t)NV * NI * NO];   // 8 MB, NATURAL layout [v][i][o]
__device__ __half g_adj16[NV * NV];
__device__ float g_sum[NV * NO];
__device__ float g_sqs[NV * NO];
__device__ float g_s[NV * NO];
__device__ float g_t[NV * NO];

// ---------------------------------------------------------------------------
// Helpers (baseline PTX only)
// ---------------------------------------------------------------------------
__device__ __forceinline__ uint32_t smem_u32(const void* p) {
    uint32_t a;
    asm("{ .reg .u64 t; cvta.to.shared.u64 t, %1; cvt.u32.u64 %0, t; }"
        : "=r"(a) : "l"(p));
    return a;
}
#define SWZ(off) ((uint32_t)(off) ^ ((((uint32_t)(off)) >> 3) & 0x70))  // 128B rows

__device__ __forceinline__ void ldsm_x4(uint32_t* r, uint32_t addr) {
    asm volatile("ldmatrix.sync.aligned.m8n8.x4.shared.b16 {%0,%1,%2,%3}, [%4];"
                 : "=r"(r[0]), "=r"(r[1]), "=r"(r[2]), "=r"(r[3]) : "r"(addr));
}
__device__ __forceinline__ void ldsm_x2t(uint32_t* r, uint32_t addr) {
    asm volatile("ldmatrix.sync.aligned.m8n8.x2.trans.shared.b16 {%0,%1}, [%2];"
                 : "=r"(r[0]), "=r"(r[1]) : "r"(addr));
}
__device__ __forceinline__ void mma_f16(float* d, const uint32_t* a,
                                        const uint32_t* b) {
    asm volatile(
        "mma.sync.aligned.m16n8k16.row.col.f32.f16.f16.f32 "
        "{%0,%1,%2,%3}, {%4,%5,%6,%7}, {%8,%9}, {%0,%1,%2,%3};"
        : "+f"(d[0]), "+f"(d[1]), "+f"(d[2]), "+f"(d[3])
        : "r"(a[0]), "r"(a[1]), "r"(a[2]), "r"(a[3]), "r"(b[0]), "r"(b[1]));
}
__device__ __forceinline__ void cp16(uint32_t smem, const void* g) {
    asm volatile("cp.async.cg.shared.global [%0], [%1], 16;"
                 :: "r"(smem), "l"(g) : "memory");
}
#define CP_COMMIT() asm volatile("cp.async.commit_group;" ::: "memory")
#define CP_WAIT(N)  asm volatile("cp.async.wait_group %0;" :: "n"(N) : "memory")

// ---------------------------------------------------------------------------
// Kernel A: W -> fp16, NATURAL layout (pure cast, coalesced). grid 4096 x 256.
// ---------------------------------------------------------------------------
__global__ __launch_bounds__(256) void convert_W(const float* __restrict__ W) {
    size_t i4 = (size_t)blockIdx.x * 256 + threadIdx.x;  // float4 index
    float4 x = ((const float4*)W)[i4];
    __half2 p0 = __floats2half2_rn(x.x, x.y);
    __half2 p1 = __floats2half2_rn(x.z, x.w);
    ((uint2*)g_W16)[i4] = make_uint2(*(uint32_t*)&p0, *(uint32_t*)&p1);
}

// ---------------------------------------------------------------------------
// Kernel A2: adj -> fp16 AND zero stats accumulators. grid 16 x 256.
// ---------------------------------------------------------------------------
__global__ void convert_adj(const float* __restrict__ adj) {
    int i = blockIdx.x * 256 + threadIdx.x;   // 0..4095
    g_adj16[i] = __float2half_rn(adj[i]);
    ((float4*)g_sum)[i] = make_float4(0.f, 0.f, 0.f, 0.f);
    ((float4*)g_sqs)[i] = make_float4(0.f, 0.f, 0.f, 0.f);
}

// ---------------------------------------------------------------------------
// Kernel B: pure-fp16 GEMM, B loaded from natural [k][n] layout via ldsm.trans.
// grid (NB/128, NO/128, NV), block 256 (8 warps), tile 128x128, K-chunk 64.
// smem: A 16KB (SW128 rows) + B 64 rows x 272B pitch = 17KB -> occ 2.
// ---------------------------------------------------------------------------
static constexpr int A_OFF = 0;
static constexpr int B_OFF = 16384;
static constexpr int BPITCH = 272;         // 256B row + 16B shift (conflict-free)
static constexpr int GEMM_DSMEM = 16384 + 64 * BPITCH + 1024;

__device__ __forceinline__ void load_A_regs(float4* areg,
                                            const float* __restrict__ feat,
                                            int m0, int v, int k0, int t) {
#pragma unroll
    for (int r = 0; r < 8; r++) {
        int idx = t + r * 256;            // 0..2047 float4s (128m x 64k)
        int m = idx >> 4, kq = idx & 15;
        areg[r] = *(const float4*)(feat +
                   ((size_t)(m0 + m) * NV + v) * NI + k0 + kq * 4);
    }
}
__device__ __forceinline__ void store_A_smem(char* buf, const float4* areg,
                                             int t) {
#pragma unroll
    for (int r = 0; r < 8; r++) {
        int idx = t + r * 256;
        int m = idx >> 4, kq = idx & 15;
        float4 x = areg[r];
        __half2 p0 = __floats2half2_rn(x.x, x.y);
        __half2 p1 = __floats2half2_rn(x.z, x.w);
        uint32_t off = SWZ(m * 128 + kq * 8);
        *(uint2*)(buf + A_OFF + off) =
            make_uint2(*(uint32_t*)&p0, *(uint32_t*)&p1);
    }
}
// B tile: 64 k-rows x 128 n-cols fp16, natural row-major [k][n], pitch 272B.
__device__ __forceinline__ void issue_B(uint32_t sb,
                                        const __half* __restrict__ Wp,
                                        int k0, int t) {
#pragma unroll
    for (int r = 0; r < 4; r++) {
        int idx = t + r * 256;            // 0..1023: 64 rows x 16 chunks
        int k = idx >> 4, c16 = idx & 15;
        cp16(sb + B_OFF + k * BPITCH + c16 * 16,
             Wp + (size_t)(k0 + k) * NO + c16 * 8);
    }
}

__global__ __launch_bounds__(256, 2) void gemm_mma(const float* __restrict__ feat,
                                                   const float* __restrict__ bias) {
    extern __shared__ char dynraw[];
    uint32_t rawa = smem_u32(dynraw);
    char* smb = dynraw + (((rawa + 1023) & ~1023u) - rawa);
    const uint32_t sb = smem_u32(smb);

    const int v  = blockIdx.z;
    const int m0 = blockIdx.x * 128;
    const int n0 = blockIdx.y * 128;
    const int t  = threadIdx.x;
    const int lane = t & 31;
    const int w = t >> 5;
    const int mw = (w >> 2) * 64;
    const int nw = (w & 3) * 32;

    float acc[4][4][4];
#pragma unroll
    for (int i = 0; i < 4; i++)
#pragma unroll
        for (int j = 0; j < 4; j++)
#pragma unroll
            for (int q = 0; q < 4; q++) acc[i][j][q] = 0.f;

    // natural layout: W16[v][i][o]; tile base at column n0
    const __half* Wp = g_W16 + (size_t)v * NI * NO + n0;

    float4 areg[8];
    load_A_regs(areg, feat, m0, v, 0, t);

#pragma unroll
    for (int c = 0; c < 4; c++) {
        if (c) __syncthreads();            // prev chunk consumers done
        issue_B(sb, Wp, c * 64, t);        // cp.async into the single stage
        CP_COMMIT();
        store_A_smem(smb, areg, t);        // cvt+STS overlaps cp.async
        if (c < 3) load_A_regs(areg, feat, m0, v, (c + 1) * 64, t);  // prefetch
        CP_WAIT(0);
        __syncthreads();

#pragma unroll
        for (int ks = 0; ks < 4; ks++) {
            // B fragments via ldmatrix.trans on [k][n] rows (mix-proven pattern)
            uint32_t bh[4][2];
            uint32_t brow = sb + B_OFF + (ks * 16 + (lane & 15)) * BPITCH;
#pragma unroll
            for (int nt = 0; nt < 4; nt++) {
                ldsm_x2t(bh[nt], brow + (nw + nt * 8) * 2);
            }
            int arow = mw + (lane & 7) + ((lane >> 3) & 1) * 8;
            int ak = ks * 16 + ((lane >> 4) & 1) * 8;
#pragma unroll
            for (int mt = 0; mt < 4; mt++) {
                uint32_t ra[4];
                ldsm_x4(ra, sb + A_OFF + SWZ((arow + mt * 16) * 128 + ak * 2));
#pragma unroll
                for (int nt = 0; nt < 4; nt++) {
                    mma_f16(acc[mt][nt], ra, bh[nt]);
                }
            }
        }
    }

    // ---- epilogue: bias + store h (fp16) + shuffle-reduced column stats
#pragma unroll
    for (int nt = 0; nt < 4; nt++) {
        const int nl = nw + nt * 8 + (lane & 3) * 2;   // col in block tile (even)
        const int n = n0 + nl;
        float2 bv = *(const float2*)(bias + v * NO + n);
        float2 sum2 = make_float2(0.f, 0.f), sq2 = make_float2(0.f, 0.f);
#pragma unroll
        for (int mt = 0; mt < 4; mt++) {
            int mlo = m0 + mw + mt * 16 + (lane >> 2);
            float2 o0, o1;
            o0.x = acc[mt][nt][0] + bv.x;
            o0.y = acc[mt][nt][1] + bv.y;
            o1.x = acc[mt][nt][2] + bv.x;
            o1.y = acc[mt][nt][3] + bv.y;
            __half2 p0 = __floats2half2_rn(o0.x, o0.y);
            __half2 p1 = __floats2half2_rn(o1.x, o1.y);
            *(uint32_t*)(g_h16 + (size_t)mlo * (NV * NO) + v * NO + n) =
                *(uint32_t*)&p0;
            *(uint32_t*)(g_h16 + (size_t)(mlo + 8) * (NV * NO) + v * NO + n) =
                *(uint32_t*)&p1;
            sum2.x += o0.x + o1.x;
            sum2.y += o0.y + o1.y;
            sq2.x += fmaf(o0.x, o0.x, o1.x * o1.x);
            sq2.y += fmaf(o0.y, o0.y, o1.y * o1.y);
        }
#pragma unroll
        for (int msk = 4; msk <= 16; msk <<= 1) {
            sum2.x += __shfl_xor_sync(0xffffffffu, sum2.x, msk);
            sum2.y += __shfl_xor_sync(0xffffffffu, sum2.y, msk);
            sq2.x  += __shfl_xor_sync(0xffffffffu, sq2.x, msk);
            sq2.y  += __shfl_xor_sync(0xffffffffu, sq2.y, msk);
        }
        if (lane < 4) {
            atomicAdd(&g_sum[v * NO + n],     sum2.x);
            atomicAdd(&g_sum[v * NO + n + 1], sum2.y);
            atomicAdd(&g_sqs[v * NO + n],     sq2.x);
            atomicAdd(&g_sqs[v * NO + n + 1], sq2.y);
        }
    }
}

// ---------------------------------------------------------------------------
// Kernel C: finalize BN fold
// ---------------------------------------------------------------------------
__global__ __launch_bounds__(256) void stats_fin(const float* __restrict__ gamma,
                                                 const float* __restrict__ beta) {
    const int col = blockIdx.x * 256 + threadIdx.x;
    float mean = g_sum[col] * (1.f / NB);
    float var  = g_sqs[col] * (1.f / NB) - mean * mean;
    float s    = gamma[col] * rsqrtf(var + EPS);
    g_s[col] = s;
    g_t[col] = fmaf(-mean, s, beta[col]);
}

// ---------------------------------------------------------------------------
// Kernel D: tensorized mix, 1-term fp16: adj single, hs = s*h+t single fp16.
// out[b,u,o] = relu( sum_v adj[u,v] * hs[v,o] )
// ---------------------------------------------------------------------------
static constexpr int OPAD = 264;                 // hs row stride (fp16 elems)
static constexpr int HS_OFF = 0;                 // 64*264*2 = 33792 B
static constexpr int ADJ_OFF = 33792;            // 64 rows x 72 elems x 2B
static constexpr int MIX_DSMEM = 43008 + 1024;

__global__ __launch_bounds__(256, 2) void mix_tc(float* __restrict__ out) {
    extern __shared__ char dynraw[];
    uint32_t rawa = smem_u32(dynraw);
    char* smb = dynraw + (((rawa + 1023) & ~1023u) - rawa);
    const uint32_t sbase = smem_u32(smb);

    const int b = blockIdx.x;
    const int t = threadIdx.x;
    const int lane = t & 31;
    const int w = t >> 5;

    // ---- stage hs = s*h + t (from fp16 h), single fp16, [v][OPAD]
    const uint2*  h2 = (const uint2*)(g_h16 + (size_t)b * NV * NO);  // 4 halves
    const float4* s4 = (const float4*)g_s;
    const float4* t4 = (const float4*)g_t;
#pragma unroll
    for (int r = 0; r < 16; r++) {
        int idx = t + r * 256;            // 0..4095 (4 elems each)
        int v = idx >> 6, oq = idx & 63;
        uint2 hp = h2[idx];
        __half2 ha = *(__half2*)&hp.x, hb = *(__half2*)&hp.y;
        float4 sv = s4[idx], tv = t4[idx];
        __half2 p0 = __floats2half2_rn(fmaf(__half2float(ha.x), sv.x, tv.x),
                                       fmaf(__half2float(ha.y), sv.y, tv.y));
        __half2 p1 = __floats2half2_rn(fmaf(__half2float(hb.x), sv.z, tv.z),
                                       fmaf(__half2float(hb.y), sv.w, tv.w));
        uint32_t off = (uint32_t)(v * (OPAD * 2) + oq * 8);
        *(uint2*)(smb + HS_OFF + off) =
            make_uint2(*(uint32_t*)&p0, *(uint32_t*)&p1);
    }
    // ---- stage adj (single fp16), [u][72] rows
#pragma unroll
    for (int r = 0; r < 8; r++) {
        int idx = t + r * 256;            // 0..2047 uint32s (2 fp16 each)
        int u = idx >> 5, q = idx & 31;
        *(uint32_t*)(smb + ADJ_OFF + u * 144 + q * 4) =
            ((const uint32_t*)g_adj16)[idx];
    }
    __syncthreads();

    const int mw = (w >> 1) * 16;     // u tile (4 tiles of 16)
    const int nw = (w & 1) * 128;     // o half

    float acc[16][4];
#pragma unroll
    for (int i = 0; i < 16; i++)
#pragma unroll
        for (int q = 0; q < 4; q++) acc[i][q] = 0.f;

#pragma unroll
    for (int ks = 0; ks < 4; ks++) {
        uint32_t ah[4];
        uint32_t aaddr = sbase + ADJ_OFF + (mw + (lane & 15)) * 144 +
                         (ks * 16 + (lane >> 4) * 8) * 2;
        ldsm_x4(ah, aaddr);

        uint32_t brow = sbase + HS_OFF + (ks * 16 + (lane & 15)) * (OPAD * 2);
#pragma unroll
        for (int nt = 0; nt < 16; nt++) {
            uint32_t bh[2];
            ldsm_x2t(bh, brow + (nw + nt * 8) * 2);
            mma_f16(acc[nt], ah, bh);
        }
    }

    // ---- epilogue: relu + store
    float* ob = out + (size_t)b * NV * NO;
    const int u0 = mw + (lane >> 2);
#pragma unroll
    for (int nt = 0; nt < 16; nt++) {
        int o = nw + nt * 8 + (lane & 3) * 2;
        float2 r0, r1;
        r0.x = fmaxf(acc[nt][0], 0.f);
        r0.y = fmaxf(acc[nt][1], 0.f);
        r1.x = fmaxf(acc[nt][2], 0.f);
        r1.y = fmaxf(acc[nt][3], 0.f);
        *(float2*)(ob + (size_t)u0 * NO + o) = r0;
        *(float2*)(ob + (size_t)(u0 + 8) * NO + o) = r1;
    }
}

// ---------------------------------------------------------------------------
extern "C" void kernel_launch(void* const* d_in, const int* in_sizes, int n_in,
                              void* d_out, int out_size) {
    const float* feat  = (const float*)d_in[0];
    const float* adj   = (const float*)d_in[1];
    const float* W     = (const float*)d_in[2];
    const float* bias  = (const float*)d_in[3];
    const float* gamma = (const float*)d_in[4];
    const float* beta  = (const float*)d_in[5];
    float* out = (float*)d_out;

    cudaFuncSetAttribute(gemm_mma, cudaFuncAttributeMaxDynamicSharedMemorySize,
                         GEMM_DSMEM);
    cudaFuncSetAttribute(mix_tc, cudaFuncAttributeMaxDynamicSharedMemorySize,
                         MIX_DSMEM);

    convert_W<<<4096, 256>>>(W);     // NV*NI*NO/4 float4s / 256
    convert_adj<<<16, 256>>>(adj);   // also zeroes g_sum/g_sqs
    gemm_mma<<<dim3(NB / 128, NO / 128, NV), 256, GEMM_DSMEM>>>(feat, bias);
    stats_fin<<<64, 256>>>(gamma, beta);
    mix_tc<<<NB, 256, MIX_DSMEM>>>(out);
}

// round 16
// speedup vs baseline: 1.6970x; 1.0426x over previous
#include <cuda_runtime.h>
#include <cuda_bf16.h>
#include <cuda_fp16.h>
#include <cstdint>

#define NB 1024
#define NV 64
#define NI 256
#define NO 256
constexpr float EPS = 1e-5f;

// ---------------------------------------------------------------------------
// Device scratch
// ---------------------------------------------------------------------------
__device__ __half g_h16[(size_t)NB * NV * NO];   // 32 MB: h (fp16)
__device__ __half g_W16[(size_t)NV * NI * NO];   // 8 MB, NATURAL layout [v][i][o]
__device__ __half g_adj16[NV * NV];
__device__ float g_sum[NV * NO];
__device__ float g_sqs[NV * NO];
__device__ float g_s[NV * NO];
__device__ float g_t[NV * NO];

// ---------------------------------------------------------------------------
// Helpers (baseline PTX only)
// ---------------------------------------------------------------------------
__device__ __forceinline__ uint32_t smem_u32(const void* p) {
    uint32_t a;
    asm("{ .reg .u64 t; cvta.to.shared.u64 t, %1; cvt.u32.u64 %0, t; }"
        : "=r"(a) : "l"(p));
    return a;
}
#define SWZ(off) ((uint32_t)(off) ^ ((((uint32_t)(off)) >> 3) & 0x70))  // 128B rows

__device__ __forceinline__ void ldsm_x4(uint32_t* r, uint32_t addr) {
    asm volatile("ldmatrix.sync.aligned.m8n8.x4.shared.b16 {%0,%1,%2,%3}, [%4];"
                 : "=r"(r[0]), "=r"(r[1]), "=r"(r[2]), "=r"(r[3]) : "r"(addr));
}
__device__ __forceinline__ void ldsm_x2t(uint32_t* r, uint32_t addr) {
    asm volatile("ldmatrix.sync.aligned.m8n8.x2.trans.shared.b16 {%0,%1}, [%2];"
                 : "=r"(r[0]), "=r"(r[1]) : "r"(addr));
}
__device__ __forceinline__ void mma_f16(float* d, const uint32_t* a,
                                        const uint32_t* b) {
    asm volatile(
        "mma.sync.aligned.m16n8k16.row.col.f32.f16.f16.f32 "
        "{%0,%1,%2,%3}, {%4,%5,%6,%7}, {%8,%9}, {%0,%1,%2,%3};"
        : "+f"(d[0]), "+f"(d[1]), "+f"(d[2]), "+f"(d[3])
        : "r"(a[0]), "r"(a[1]), "r"(a[2]), "r"(a[3]), "r"(b[0]), "r"(b[1]));
}
__device__ __forceinline__ void cp16(uint32_t smem, const void* g) {
    asm volatile("cp.async.cg.shared.global [%0], [%1], 16;"
                 :: "r"(smem), "l"(g) : "memory");
}
#define CP_COMMIT() asm volatile("cp.async.commit_group;" ::: "memory")
#define CP_WAIT(N)  asm volatile("cp.async.wait_group %0;" :: "n"(N) : "memory")

// ---------------------------------------------------------------------------
// Kernel A: W -> fp16, NATURAL layout (pure cast, coalesced). grid 4096 x 256.
// ---------------------------------------------------------------------------
__global__ __launch_bounds__(256) void convert_W(const float* __restrict__ W) {
    size_t i4 = (size_t)blockIdx.x * 256 + threadIdx.x;  // float4 index
    float4 x = ((const float4*)W)[i4];
    __half2 p0 = __floats2half2_rn(x.x, x.y);
    __half2 p1 = __floats2half2_rn(x.z, x.w);
    ((uint2*)g_W16)[i4] = make_uint2(*(uint32_t*)&p0, *(uint32_t*)&p1);
}

// ---------------------------------------------------------------------------
// Kernel A2: adj -> fp16 AND zero stats accumulators. grid 16 x 256.
// ---------------------------------------------------------------------------
__global__ void convert_adj(const float* __restrict__ adj) {
    int i = blockIdx.x * 256 + threadIdx.x;   // 0..4095
    g_adj16[i] = __float2half_rn(adj[i]);
    ((float4*)g_sum)[i] = make_float4(0.f, 0.f, 0.f, 0.f);
    ((float4*)g_sqs)[i] = make_float4(0.f, 0.f, 0.f, 0.f);
}

// ---------------------------------------------------------------------------
// Kernel B: pure-fp16 GEMM, 2-stage double buffer, ONE sync per K-chunk.
// grid (NB/128, NO/128, NV), block 256 (8 warps), tile 128x128, K-chunk 64.
// Stage: A 16KB (SW128 rows) + B 64 rows x 272B = 33792 B; 2 stages -> occ 2.
// ---------------------------------------------------------------------------
static constexpr int A_OFF = 0;
static constexpr int B_OFF = 16384;
static constexpr int BPITCH = 272;         // 256B row + 16B shift (conflict-free)
static constexpr int STG = 16384 + 64 * BPITCH;    // 33792
static constexpr int GEMM_DSMEM = 2 * STG + 1024;

__device__ __forceinline__ void load_A_regs(float4* areg,
                                            const float* __restrict__ feat,
                                            int m0, int v, int k0, int t) {
#pragma unroll
    for (int r = 0; r < 8; r++) {
        int idx = t + r * 256;            // 0..2047 float4s (128m x 64k)
        int m = idx >> 4, kq = idx & 15;
        areg[r] = *(const float4*)(feat +
                   ((size_t)(m0 + m) * NV + v) * NI + k0 + kq * 4);
    }
}
__device__ __forceinline__ void store_A_smem(char* buf, const float4* areg,
                                             int t) {
#pragma unroll
    for (int r = 0; r < 8; r++) {
        int idx = t + r * 256;
        int m = idx >> 4, kq = idx & 15;
        float4 x = areg[r];
        __half2 p0 = __floats2half2_rn(x.x, x.y);
        __half2 p1 = __floats2half2_rn(x.z, x.w);
        uint32_t off = SWZ(m * 128 + kq * 8);
        *(uint2*)(buf + A_OFF + off) =
            make_uint2(*(uint32_t*)&p0, *(uint32_t*)&p1);
    }
}
// B tile: 64 k-rows x 128 n-cols fp16, natural row-major [k][n], pitch 272B.
__device__ __forceinline__ void issue_B(uint32_t sb,
                                        const __half* __restrict__ Wp,
                                        int k0, int t) {
#pragma unroll
    for (int r = 0; r < 4; r++) {
        int idx = t + r * 256;            // 0..1023: 64 rows x 16 chunks
        int k = idx >> 4, c16 = idx & 15;
        cp16(sb + B_OFF + k * BPITCH + c16 * 16,
             Wp + (size_t)(k0 + k) * NO + c16 * 8);
    }
}

__global__ __launch_bounds__(256, 2) void gemm_mma(const float* __restrict__ feat,
                                                   const float* __restrict__ bias) {
    extern __shared__ char dynraw[];
    uint32_t rawa = smem_u32(dynraw);
    char* smb = dynraw + (((rawa + 1023) & ~1023u) - rawa);
    const uint32_t sb0 = smem_u32(smb);

    const int v  = blockIdx.z;
    const int m0 = blockIdx.x * 128;
    const int n0 = blockIdx.y * 128;
    const int t  = threadIdx.x;
    const int lane = t & 31;
    const int w = t >> 5;
    const int mw = (w >> 2) * 64;
    const int nw = (w & 3) * 32;

    float acc[4][4][4];
#pragma unroll
    for (int i = 0; i < 4; i++)
#pragma unroll
        for (int j = 0; j < 4; j++)
#pragma unroll
            for (int q = 0; q < 4; q++) acc[i][j][q] = 0.f;

    // natural layout: W16[v][i][o]; tile base at column n0
    const __half* Wp = g_W16 + (size_t)v * NI * NO + n0;

    // ---- prologue: stage0 gets chunk0 (B in flight, A stored); A1 in regs
    float4 areg[8];
    load_A_regs(areg, feat, m0, v, 0, t);
    issue_B(sb0, Wp, 0, t);
    CP_COMMIT();                               // group: B0
    store_A_smem(smb, areg, t);
    load_A_regs(areg, feat, m0, v, 64, t);     // A1 -> regs

#pragma unroll
    for (int c = 0; c < 4; c++) {
        const uint32_t sb = sb0 + (c & 1) * STG;

        CP_WAIT(0);            // B_c landed (only outstanding group)
        __syncthreads();       // B_c visible; free stage = consumers of c-1 done

        if (c < 3) {
            char* nbuf = smb + ((c + 1) & 1) * STG;
            store_A_smem(nbuf, areg, t);                   // A(c+1)
            if (c < 2) load_A_regs(areg, feat, m0, v, (c + 2) * 64, t);
            issue_B(sb0 + ((c + 1) & 1) * STG, Wp, (c + 1) * 64, t);
            CP_COMMIT();                                   // B(c+1), hidden by compute
        }

        // ---- compute chunk c (4 k-steps of 16)
#pragma unroll
        for (int ks = 0; ks < 4; ks++) {
            uint32_t bh[4][2];
            uint32_t brow = sb + B_OFF + (ks * 16 + (lane & 15)) * BPITCH;
#pragma unroll
            for (int nt = 0; nt < 4; nt++) {
                ldsm_x2t(bh[nt], brow + (nw + nt * 8) * 2);
            }
            int arow = mw + (lane & 7) + ((lane >> 3) & 1) * 8;
            int ak = ks * 16 + ((lane >> 4) & 1) * 8;
#pragma unroll
            for (int mt = 0; mt < 4; mt++) {
                uint32_t ra[4];
                ldsm_x4(ra, sb + A_OFF + SWZ((arow + mt * 16) * 128 + ak * 2));
#pragma unroll
                for (int nt = 0; nt < 4; nt++) {
                    mma_f16(acc[mt][nt], ra, bh[nt]);
                }
            }
        }
    }

    // ---- epilogue: bias + store h (fp16) + shuffle-reduced column stats
#pragma unroll
    for (int nt = 0; nt < 4; nt++) {
        const int nl = nw + nt * 8 + (lane & 3) * 2;   // col in block tile (even)
        const int n = n0 + nl;
        float2 bv = *(const float2*)(bias + v * NO + n);
        float2 sum2 = make_float2(0.f, 0.f), sq2 = make_float2(0.f, 0.f);
#pragma unroll
        for (int mt = 0; mt < 4; mt++) {
            int mlo = m0 + mw + mt * 16 + (lane >> 2);
            float2 o0, o1;
            o0.x = acc[mt][nt][0] + bv.x;
            o0.y = acc[mt][nt][1] + bv.y;
            o1.x = acc[mt][nt][2] + bv.x;
            o1.y = acc[mt][nt][3] + bv.y;
            __half2 p0 = __floats2half2_rn(o0.x, o0.y);
            __half2 p1 = __floats2half2_rn(o1.x, o1.y);
            *(uint32_t*)(g_h16 + (size_t)mlo * (NV * NO) + v * NO + n) =
                *(uint32_t*)&p0;
            *(uint32_t*)(g_h16 + (size_t)(mlo + 8) * (NV * NO) + v * NO + n) =
                *(uint32_t*)&p1;
            sum2.x += o0.x + o1.x;
            sum2.y += o0.y + o1.y;
            sq2.x += fmaf(o0.x, o0.x, o1.x * o1.x);
            sq2.y += fmaf(o0.y, o0.y, o1.y * o1.y);
        }
#pragma unroll
        for (int msk = 4; msk <= 16; msk <<= 1) {
            sum2.x += __shfl_xor_sync(0xffffffffu, sum2.x, msk);
            sum2.y += __shfl_xor_sync(0xffffffffu, sum2.y, msk);
            sq2.x  += __shfl_xor_sync(0xffffffffu, sq2.x, msk);
            sq2.y  += __shfl_xor_sync(0xffffffffu, sq2.y, msk);
        }
        if (lane < 4) {
            atomicAdd(&g_sum[v * NO + n],     sum2.x);
            atomicAdd(&g_sum[v * NO + n + 1], sum2.y);
            atomicAdd(&g_sqs[v * NO + n],     sq2.x);
            atomicAdd(&g_sqs[v * NO + n + 1], sq2.y);
        }
    }
}

// ---------------------------------------------------------------------------
// Kernel C: finalize BN fold
// ---------------------------------------------------------------------------
__global__ __launch_bounds__(256) void stats_fin(const float* __restrict__ gamma,
                                                 const float* __restrict__ beta) {
    const int col = blockIdx.x * 256 + threadIdx.x;
    float mean = g_sum[col] * (1.f / NB);
    float var  = g_sqs[col] * (1.f / NB) - mean * mean;
    float s    = gamma[col] * rsqrtf(var + EPS);
    g_s[col] = s;
    g_t[col] = fmaf(-mean, s, beta[col]);
}

// ---------------------------------------------------------------------------
// Kernel D: tensorized mix, 1-term fp16 (unchanged from R15, ~15us)
// ---------------------------------------------------------------------------
static constexpr int OPAD = 264;                 // hs row stride (fp16 elems)
static constexpr int HS_OFF = 0;                 // 64*264*2 = 33792 B
static constexpr int ADJ_OFF = 33792;            // 64 rows x 72 elems x 2B
static constexpr int MIX_DSMEM = 43008 + 1024;

__global__ __launch_bounds__(256, 2) void mix_tc(float* __restrict__ out) {
    extern __shared__ char dynraw[];
    uint32_t rawa = smem_u32(dynraw);
    char* smb = dynraw + (((rawa + 1023) & ~1023u) - rawa);
    const uint32_t sbase = smem_u32(smb);

    const int b = blockIdx.x;
    const int t = threadIdx.x;
    const int lane = t & 31;
    const int w = t >> 5;

    // ---- stage hs = s*h + t (from fp16 h), single fp16, [v][OPAD]
    const uint2*  h2 = (const uint2*)(g_h16 + (size_t)b * NV * NO);  // 4 halves
    const float4* s4 = (const float4*)g_s;
    const float4* t4 = (const float4*)g_t;
#pragma unroll
    for (int r = 0; r < 16; r++) {
        int idx = t + r * 256;            // 0..4095 (4 elems each)
        int v = idx >> 6, oq = idx & 63;
        uint2 hp = h2[idx];
        __half2 ha = *(__half2*)&hp.x, hb = *(__half2*)&hp.y;
        float4 sv = s4[idx], tv = t4[idx];
        __half2 p0 = __floats2half2_rn(fmaf(__half2float(ha.x), sv.x, tv.x),
                                       fmaf(__half2float(ha.y), sv.y, tv.y));
        __half2 p1 = __floats2half2_rn(fmaf(__half2float(hb.x), sv.z, tv.z),
                                       fmaf(__half2float(hb.y), sv.w, tv.w));
        uint32_t off = (uint32_t)(v * (OPAD * 2) + oq * 8);
        *(uint2*)(smb + HS_OFF + off) =
            make_uint2(*(uint32_t*)&p0, *(uint32_t*)&p1);
    }
    // ---- stage adj (single fp16), [u][72] rows
#pragma unroll
    for (int r = 0; r < 8; r++) {
        int idx = t + r * 256;            // 0..2047 uint32s (2 fp16 each)
        int u = idx >> 5, q = idx & 31;
        *(uint32_t*)(smb + ADJ_OFF + u * 144 + q * 4) =
            ((const uint32_t*)g_adj16)[idx];
    }
    __syncthreads();

    const int mw = (w >> 1) * 16;     // u tile (4 tiles of 16)
    const int nw = (w & 1) * 128;     // o half

    float acc[16][4];
#pragma unroll
    for (int i = 0; i < 16; i++)
#pragma unroll
        for (int q = 0; q < 4; q++) acc[i][q] = 0.f;

#pragma unroll
    for (int ks = 0; ks < 4; ks++) {
        uint32_t ah[4];
        uint32_t aaddr = sbase + ADJ_OFF + (mw + (lane & 15)) * 144 +
                         (ks * 16 + (lane >> 4) * 8) * 2;
        ldsm_x4(ah, aaddr);

        uint32_t brow = sbase + HS_OFF + (ks * 16 + (lane & 15)) * (OPAD * 2);
#pragma unroll
        for (int nt = 0; nt < 16; nt++) {
            uint32_t bh[2];
            ldsm_x2t(bh, brow + (nw + nt * 8) * 2);
            mma_f16(acc[nt], ah, bh);
        }
    }

    // ---- epilogue: relu + store
    float* ob = out + (size_t)b * NV * NO;
    const int u0 = mw + (lane >> 2);
#pragma unroll
    for (int nt = 0; nt < 16; nt++) {
        int o = nw + nt * 8 + (lane & 3) * 2;
        float2 r0, r1;
        r0.x = fmaxf(acc[nt][0], 0.f);
        r0.y = fmaxf(acc[nt][1], 0.f);
        r1.x = fmaxf(acc[nt][2], 0.f);
        r1.y = fmaxf(acc[nt][3], 0.f);
        *(float2*)(ob + (size_t)u0 * NO + o) = r0;
        *(float2*)(ob + (size_t)(u0 + 8) * NO + o) = r1;
    }
}

// ---------------------------------------------------------------------------
extern "C" void kernel_launch(void* const* d_in, const int* in_sizes, int n_in,
                              void* d_out, int out_size) {
    const float* feat  = (const float*)d_in[0];
    const float* adj   = (const float*)d_in[1];
    const float* W     = (const float*)d_in[2];
    const float* bias  = (const float*)d_in[3];
    const float* gamma = (const float*)d_in[4];
    const float* beta  = (const float*)d_in[5];
    float* out = (float*)d_out;

    cudaFuncSetAttribute(gemm_mma, cudaFuncAttributeMaxDynamicSharedMemorySize,
                         GEMM_DSMEM);
    cudaFuncSetAttribute(mix_tc, cudaFuncAttributeMaxDynamicSharedMemorySize,
                         MIX_DSMEM);

    convert_W<<<4096, 256>>>(W);     // NV*NI*NO/4 float4s / 256
    convert_adj<<<16, 256>>>(adj);   // also zeroes g_sum/g_sqs
    gemm_mma<<<dim3(NB / 128, NO / 128, NV), 256, GEMM_DSMEM>>>(feat, bias);
    stats_fin<<<64, 256>>>(gamma, beta);
    mix_tc<<<NB, 256, MIX_DSMEM>>>(out);
}